// round 1
// baseline (speedup 1.0000x reference)
#include <cuda_runtime.h>
#include <cstdint>

#define N_NODES_C 2048
#define N_EDGES_C 32768
#define KDIM 512

// ---------------- scratch (static device globals: allowed) ----------------
__device__ int   g_send_idx[N_EDGES_C];
__device__ int   g_recv_idx[N_EDGES_C];
__device__ float g_hid[(size_t)N_EDGES_C * 512];   // edge hidden, 64MB
__device__ float g_agg[N_NODES_C * 256];           // aggregated messages
__device__ float g_h1[N_NODES_C * 512];
__device__ float g_h2[N_NODES_C * 512];

// ---------------- index extraction from one-hot matrices ----------------
__global__ void extract_idx_kernel(const float* __restrict__ rel_rec,
                                   const float* __restrict__ rel_send) {
    int wg   = (blockIdx.x * blockDim.x + threadIdx.x) >> 5;
    int lane = threadIdx.x & 31;
    const float* mat;
    int* out;
    int e;
    if (wg < N_EDGES_C) { mat = rel_rec;  out = g_recv_idx; e = wg; }
    else                { mat = rel_send; out = g_send_idx; e = wg - N_EDGES_C; }

    const float4* row = reinterpret_cast<const float4*>(mat + (size_t)e * N_NODES_C);
    int found = 0;
#pragma unroll
    for (int i = 0; i < N_NODES_C / 128; i++) {
        float4 v = row[lane + i * 32];
        int base = (lane + i * 32) * 4;
        if (v.x != 0.f) found = base;
        if (v.y != 0.f) found = base + 1;
        if (v.z != 0.f) found = base + 2;
        if (v.w != 0.f) found = base + 3;
    }
#pragma unroll
    for (int o = 16; o > 0; o >>= 1)
        found = max(found, __shfl_xor_sync(0xffffffffu, found, o));
    if (lane == 0) out[e] = found;
}

// ---------------- zero the aggregation buffer ----------------
__global__ void zero_agg_kernel() {
    int i = blockIdx.x * blockDim.x + threadIdx.x;  // one float4 each
    reinterpret_cast<float4*>(g_agg)[i] = make_float4(0.f, 0.f, 0.f, 0.f);
}

// ---------------- tf32 helpers ----------------
__device__ __forceinline__ float tf32r(float x) {
    float r;
    asm("cvt.rna.tf32.f32 %0, %1;" : "=f"(r) : "f"(x));
    return r;
}
__device__ __forceinline__ void mma_tf32(float& d0, float& d1, float& d2, float& d3,
                                         uint32_t a0, uint32_t a1, uint32_t a2, uint32_t a3,
                                         uint32_t b0, uint32_t b1) {
    asm volatile(
        "mma.sync.aligned.m16n8k8.row.col.f32.tf32.tf32.f32 "
        "{%0,%1,%2,%3}, {%4,%5,%6,%7}, {%8,%9}, {%0,%1,%2,%3};"
        : "+f"(d0), "+f"(d1), "+f"(d2), "+f"(d3)
        : "r"(a0), "r"(a1), "r"(a2), "r"(a3), "r"(b0), "r"(b1));
}

// ---------------- generic fused GEMM: C = act(A @ W^T + b) ----------------
// AMODE 0: A0 is [M, 512] plain
// AMODE 1: row r = concat(inputs[send[r]](256), inputs[recv[r]](256)); A0 = inputs
// AMODE 2: row r = concat(A0[r](256), A1[r](256))
// SCATTER: instead of store, atomicAdd into g_agg[recv_idx[row]] (N must be 256)
// RESID:   add resid[row*N+col] before store (no relu)
template <int AMODE, bool RELU, bool SCATTER, bool RESID>
__global__ __launch_bounds__(256) void gemm_tf32_kernel(
    const float* __restrict__ A0, const float* __restrict__ A1,
    const float* __restrict__ W, const float* __restrict__ bias,
    const float* __restrict__ resid, float* __restrict__ C, int N) {

    constexpr int BM = 128, BN = 64, BK = 32, LDS_ = BK + 4;  // stride 36: conflict-free frags
    __shared__ float As[BM][LDS_];
    __shared__ float Bs[BN][LDS_];
    __shared__ int   sidx_s[BM];
    __shared__ int   ridx_s[BM];

    const int tid   = threadIdx.x;
    const int lane  = tid & 31;
    const int warp  = tid >> 5;
    const int warpM = (warp & 3) * 32;
    const int warpN = (warp >> 2) * 32;
    const int blockM = blockIdx.x * BM;
    const int blockN = blockIdx.y * BN;

    if (AMODE == 1 || SCATTER) {
        if (tid < BM) {
            if (AMODE == 1) sidx_s[tid] = g_send_idx[blockM + tid];
            ridx_s[tid] = g_recv_idx[blockM + tid];
        }
        __syncthreads();
    }

    float acc[2][4][4];
#pragma unroll
    for (int mt = 0; mt < 2; mt++)
#pragma unroll
        for (int nt = 0; nt < 4; nt++)
#pragma unroll
            for (int j = 0; j < 4; j++) acc[mt][nt][j] = 0.f;

    float4 aReg[4];
    float4 bReg[2];

    auto loadA = [&](int kt) {
#pragma unroll
        for (int i = 0; i < 4; i++) {
            int f   = tid + i * 256;
            int row = f >> 3;
            int c4  = f & 7;
            int kg  = kt * BK + c4 * 4;
            const float* p;
            if (AMODE == 0) {
                p = A0 + (size_t)(blockM + row) * KDIM + kg;
            } else if (AMODE == 1) {
                int node = (kg < 256) ? sidx_s[row] : ridx_s[row];
                p = A0 + (size_t)node * 256 + (kg & 255);
            } else {
                p = (kg < 256) ? (A0 + (size_t)(blockM + row) * 256 + kg)
                               : (A1 + (size_t)(blockM + row) * 256 + (kg - 256));
            }
            aReg[i] = *reinterpret_cast<const float4*>(p);
        }
    };
    auto loadB = [&](int kt) {
#pragma unroll
        for (int i = 0; i < 2; i++) {
            int f  = tid + i * 256;
            int n  = f >> 3;
            int c4 = f & 7;
            bReg[i] = *reinterpret_cast<const float4*>(
                W + (size_t)(blockN + n) * KDIM + kt * BK + c4 * 4);
        }
    };
    auto storeTiles = [&]() {
#pragma unroll
        for (int i = 0; i < 4; i++) {
            int f = tid + i * 256, row = f >> 3, c4 = f & 7;
            As[row][c4 * 4 + 0] = tf32r(aReg[i].x);
            As[row][c4 * 4 + 1] = tf32r(aReg[i].y);
            As[row][c4 * 4 + 2] = tf32r(aReg[i].z);
            As[row][c4 * 4 + 3] = tf32r(aReg[i].w);
        }
#pragma unroll
        for (int i = 0; i < 2; i++) {
            int f = tid + i * 256, n = f >> 3, c4 = f & 7;
            Bs[n][c4 * 4 + 0] = tf32r(bReg[i].x);
            Bs[n][c4 * 4 + 1] = tf32r(bReg[i].y);
            Bs[n][c4 * 4 + 2] = tf32r(bReg[i].z);
            Bs[n][c4 * 4 + 3] = tf32r(bReg[i].w);
        }
    };

    loadA(0);
    loadB(0);
    storeTiles();
    __syncthreads();

    constexpr int NKT = KDIM / BK;  // 16
#pragma unroll 1
    for (int kt = 0; kt < NKT; kt++) {
        if (kt < NKT - 1) { loadA(kt + 1); loadB(kt + 1); }

#pragma unroll
        for (int kk = 0; kk < BK; kk += 8) {
            uint32_t a[2][4], b[4][2];
#pragma unroll
            for (int mt = 0; mt < 2; mt++) {
                int r = warpM + mt * 16 + (lane >> 2);
                int c = kk + (lane & 3);
                a[mt][0] = __float_as_uint(As[r][c]);
                a[mt][1] = __float_as_uint(As[r + 8][c]);
                a[mt][2] = __float_as_uint(As[r][c + 4]);
                a[mt][3] = __float_as_uint(As[r + 8][c + 4]);
            }
#pragma unroll
            for (int nt = 0; nt < 4; nt++) {
                int n = warpN + nt * 8 + (lane >> 2);
                int c = kk + (lane & 3);
                b[nt][0] = __float_as_uint(Bs[n][c]);
                b[nt][1] = __float_as_uint(Bs[n][c + 4]);
            }
#pragma unroll
            for (int mt = 0; mt < 2; mt++)
#pragma unroll
                for (int nt = 0; nt < 4; nt++)
                    mma_tf32(acc[mt][nt][0], acc[mt][nt][1], acc[mt][nt][2], acc[mt][nt][3],
                             a[mt][0], a[mt][1], a[mt][2], a[mt][3], b[nt][0], b[nt][1]);
        }
        __syncthreads();
        if (kt < NKT - 1) {
            storeTiles();
            __syncthreads();
        }
    }

    // epilogue
#pragma unroll
    for (int mt = 0; mt < 2; mt++) {
        int r0 = warpM + mt * 16 + (lane >> 2);
        size_t gr0 = (size_t)blockM + r0;
        size_t gr1 = gr0 + 8;
        int node0 = 0, node1 = 0;
        if (SCATTER) { node0 = ridx_s[r0]; node1 = ridx_s[r0 + 8]; }
#pragma unroll
        for (int nt = 0; nt < 4; nt++) {
            int col = blockN + warpN + nt * 8 + (lane & 3) * 2;
            float bv0 = bias[col], bv1 = bias[col + 1];
            float v0 = acc[mt][nt][0] + bv0;
            float v1 = acc[mt][nt][1] + bv1;
            float v2 = acc[mt][nt][2] + bv0;
            float v3 = acc[mt][nt][3] + bv1;
            if (RELU) {
                v0 = fmaxf(v0, 0.f); v1 = fmaxf(v1, 0.f);
                v2 = fmaxf(v2, 0.f); v3 = fmaxf(v3, 0.f);
            }
            if (SCATTER) {
                atomicAdd(&g_agg[(size_t)node0 * 256 + col],     v0);
                atomicAdd(&g_agg[(size_t)node0 * 256 + col + 1], v1);
                atomicAdd(&g_agg[(size_t)node1 * 256 + col],     v2);
                atomicAdd(&g_agg[(size_t)node1 * 256 + col + 1], v3);
            } else {
                if (RESID) {
                    v0 += resid[gr0 * N + col];
                    v1 += resid[gr0 * N + col + 1];
                    v2 += resid[gr1 * N + col];
                    v3 += resid[gr1 * N + col + 1];
                }
                float2 p0 = make_float2(v0, v1);
                float2 p1 = make_float2(v2, v3);
                *reinterpret_cast<float2*>(C + gr0 * N + col) = p0;
                *reinterpret_cast<float2*>(C + gr1 * N + col) = p1;
            }
        }
    }
}

// ---------------- launch ----------------
extern "C" void kernel_launch(void* const* d_in, const int* in_sizes, int n_in,
                              void* d_out, int out_size) {
    const float* inputs   = (const float*)d_in[0];
    const float* rel_rec  = (const float*)d_in[1];
    const float* rel_send = (const float*)d_in[2];
    const float* msg_W1   = (const float*)d_in[3];
    const float* msg_b1   = (const float*)d_in[4];
    const float* msg_W2   = (const float*)d_in[5];
    const float* msg_b2   = (const float*)d_in[6];
    const float* out_W1   = (const float*)d_in[7];
    const float* out_b1   = (const float*)d_in[8];
    const float* out_W2   = (const float*)d_in[9];
    const float* out_b2   = (const float*)d_in[10];
    const float* out_W3   = (const float*)d_in[11];
    const float* out_b3   = (const float*)d_in[12];
    float* out = (float*)d_out;

    float* hid; float* agg; float* h1; float* h2;
    cudaGetSymbolAddress((void**)&hid, g_hid);
    cudaGetSymbolAddress((void**)&agg, g_agg);
    cudaGetSymbolAddress((void**)&h1,  g_h1);
    cudaGetSymbolAddress((void**)&h2,  g_h2);

    // 1) indices from one-hot (2 * 32768 warps)
    extract_idx_kernel<<<(2 * N_EDGES_C * 32) / 256, 256>>>(rel_rec, rel_send);
    // 2) zero aggregation buffer (float4 per thread)
    zero_agg_kernel<<<(N_NODES_C * 256 / 4) / 256, 256>>>();

    // 3) edge MLP layer 1: hid = relu(concat(in[send], in[recv]) @ W1^T + b1)
    gemm_tf32_kernel<1, true, false, false>
        <<<dim3(N_EDGES_C / 128, 512 / 64), 256>>>(
            inputs, nullptr, msg_W1, msg_b1, nullptr, hid, 512);

    // 4) edge MLP layer 2 + fused scatter-add into agg
    gemm_tf32_kernel<0, true, true, false>
        <<<dim3(N_EDGES_C / 128, 256 / 64), 256>>>(
            hid, nullptr, msg_W2, msg_b2, nullptr, agg, 256);

    // 5) node MLP layer 1: h1 = relu(concat(inputs, agg) @ outW1^T + b1)
    gemm_tf32_kernel<2, true, false, false>
        <<<dim3(N_NODES_C / 128, 512 / 64), 256>>>(
            inputs, agg, out_W1, out_b1, nullptr, h1, 512);

    // 6) node MLP layer 2
    gemm_tf32_kernel<0, true, false, false>
        <<<dim3(N_NODES_C / 128, 512 / 64), 256>>>(
            h1, nullptr, out_W2, out_b2, nullptr, h2, 512);

    // 7) node MLP layer 3 + residual
    gemm_tf32_kernel<0, false, false, true>
        <<<dim3(N_NODES_C / 128, 256 / 64), 256>>>(
            h2, nullptr, out_W3, out_b3, inputs, out, 256);
}

// round 2
// speedup vs baseline: 1.2776x; 1.2776x over previous
#include <cuda_runtime.h>
#include <cuda_bf16.h>
#include <cstdint>

#define N_NODES_C 2048
#define N_EDGES_C 32768
#define KDIM 512

// ---------------- scratch (static device globals: allowed) ----------------
__device__ int            g_send_idx[N_EDGES_C];
__device__ int            g_recv_idx[N_EDGES_C];
__device__ __nv_bfloat16  g_hid[(size_t)N_EDGES_C * 512];  // edge hidden, bf16, 32MB
__device__ float          g_agg[N_NODES_C * 256];          // aggregated messages (f32 for atomics)
__device__ __nv_bfloat16  g_h1[N_NODES_C * 512];
__device__ __nv_bfloat16  g_h2[N_NODES_C * 512];

// ---------------- index extraction from one-hot matrices ----------------
__global__ void extract_idx_kernel(const float* __restrict__ rel_rec,
                                   const float* __restrict__ rel_send) {
    int wg   = (blockIdx.x * blockDim.x + threadIdx.x) >> 5;
    int lane = threadIdx.x & 31;
    const float* mat;
    int* out;
    int e;
    if (wg < N_EDGES_C) { mat = rel_rec;  out = g_recv_idx; e = wg; }
    else                { mat = rel_send; out = g_send_idx; e = wg - N_EDGES_C; }

    const float4* row = reinterpret_cast<const float4*>(mat + (size_t)e * N_NODES_C);
    int found = 0;
#pragma unroll
    for (int i = 0; i < N_NODES_C / 128; i++) {
        float4 v = row[lane + i * 32];
        int base = (lane + i * 32) * 4;
        if (v.x != 0.f) found = base;
        if (v.y != 0.f) found = base + 1;
        if (v.z != 0.f) found = base + 2;
        if (v.w != 0.f) found = base + 3;
    }
#pragma unroll
    for (int o = 16; o > 0; o >>= 1)
        found = max(found, __shfl_xor_sync(0xffffffffu, found, o));
    if (lane == 0) out[e] = found;
}

// ---------------- zero the aggregation buffer ----------------
__global__ void zero_agg_kernel() {
    int i = blockIdx.x * blockDim.x + threadIdx.x;  // one float4 each
    reinterpret_cast<float4*>(g_agg)[i] = make_float4(0.f, 0.f, 0.f, 0.f);
}

// ---------------- bf16 helpers ----------------
__device__ __forceinline__ uint32_t pk(float lo, float hi) {
    __nv_bfloat162 h = __floats2bfloat162_rn(lo, hi);
    return *reinterpret_cast<uint32_t*>(&h);
}
__device__ __forceinline__ void mma_bf16(float& d0, float& d1, float& d2, float& d3,
                                         uint32_t a0, uint32_t a1, uint32_t a2, uint32_t a3,
                                         uint32_t b0, uint32_t b1) {
    asm volatile(
        "mma.sync.aligned.m16n8k16.row.col.f32.bf16.bf16.f32 "
        "{%0,%1,%2,%3}, {%4,%5,%6,%7}, {%8,%9}, {%0,%1,%2,%3};"
        : "+f"(d0), "+f"(d1), "+f"(d2), "+f"(d3)
        : "r"(a0), "r"(a1), "r"(a2), "r"(a3), "r"(b0), "r"(b1));
}

// ---------------- generic fused GEMM: C = act(A @ W^T + b) ----------------
// AMODE 0: A0 is [M, 512] plain (f32 if !ABF, bf16 if ABF)
// AMODE 1: row r = concat(inputs[send[r]](256), inputs[recv[r]](256)); A0 = inputs (f32)
// AMODE 2: row r = concat(A0[r](256), A1[r](256)) both f32
// SCATTER: red.add into g_agg[recv_idx[row]] instead of store (N must be 256)
// RESID:   add resid[row*N+col] before store (no relu)
// OUTBF:   store C as bf16
template <int AMODE, bool RELU, bool SCATTER, bool RESID, bool ABF, bool OUTBF>
__global__ __launch_bounds__(256, 2) void gemm_bf16_kernel(
    const void* __restrict__ A0v, const float* __restrict__ A1,
    const float* __restrict__ W, const float* __restrict__ bias,
    const float* __restrict__ resid, void* __restrict__ Cv, int N) {

    constexpr int BM = 128, BN = 64, BK = 32;
    constexpr int SP = 20;  // uint32 pairs per row: 16 data + 4 pad -> conflict-free frags
    __shared__ uint32_t As[BM * SP];
    __shared__ uint32_t Bs[BN * SP];
    __shared__ int      sidx_s[BM];
    __shared__ int      ridx_s[BM];

    const int tid    = threadIdx.x;
    const int lane   = tid & 31;
    const int warp   = tid >> 5;
    const int warpM  = (warp & 3) * 32;
    const int warpN  = (warp >> 2) * 32;
    const int blockM = blockIdx.x * BM;
    const int blockN = blockIdx.y * BN;

    if (AMODE == 1 || SCATTER) {
        if (tid < BM) {
            if (AMODE == 1) sidx_s[tid] = g_send_idx[blockM + tid];
            ridx_s[tid] = g_recv_idx[blockM + tid];
        }
        __syncthreads();
    }

    float acc[2][4][4];
#pragma unroll
    for (int mt = 0; mt < 2; mt++)
#pragma unroll
        for (int nt = 0; nt < 4; nt++)
#pragma unroll
            for (int j = 0; j < 4; j++) acc[mt][nt][j] = 0.f;

    float4 aF[4];
    uint2  aH[4];
    float4 bF[2];

    auto loadA = [&](int kt) {
#pragma unroll
        for (int i = 0; i < 4; i++) {
            int f   = tid + i * 256;
            int row = f >> 3;
            int c4  = f & 7;
            int kg  = kt * BK + c4 * 4;
            if (ABF) {
                const __nv_bfloat16* p =
                    (const __nv_bfloat16*)A0v + (size_t)(blockM + row) * KDIM + kg;
                aH[i] = *reinterpret_cast<const uint2*>(p);
            } else {
                const float* A0 = (const float*)A0v;
                const float* p;
                if (AMODE == 0) {
                    p = A0 + (size_t)(blockM + row) * KDIM + kg;
                } else if (AMODE == 1) {
                    int node = (kg < 256) ? sidx_s[row] : ridx_s[row];
                    p = A0 + (size_t)node * 256 + (kg & 255);
                } else {
                    p = (kg < 256) ? (A0 + (size_t)(blockM + row) * 256 + kg)
                                   : (A1 + (size_t)(blockM + row) * 256 + (kg - 256));
                }
                aF[i] = *reinterpret_cast<const float4*>(p);
            }
        }
    };
    auto loadB = [&](int kt) {
#pragma unroll
        for (int i = 0; i < 2; i++) {
            int f  = tid + i * 256;
            int n  = f >> 3;
            int c4 = f & 7;
            bF[i] = *reinterpret_cast<const float4*>(
                W + (size_t)(blockN + n) * KDIM + kt * BK + c4 * 4);
        }
    };
    auto storeTiles = [&]() {
#pragma unroll
        for (int i = 0; i < 4; i++) {
            int f = tid + i * 256, row = f >> 3, c4 = f & 7;
            uint32_t* dst = &As[row * SP + c4 * 2];
            if (ABF) {
                dst[0] = aH[i].x;
                dst[1] = aH[i].y;
            } else {
                dst[0] = pk(aF[i].x, aF[i].y);
                dst[1] = pk(aF[i].z, aF[i].w);
            }
        }
#pragma unroll
        for (int i = 0; i < 2; i++) {
            int f = tid + i * 256, n = f >> 3, c4 = f & 7;
            uint32_t* dst = &Bs[n * SP + c4 * 2];
            dst[0] = pk(bF[i].x, bF[i].y);
            dst[1] = pk(bF[i].z, bF[i].w);
        }
    };

    loadA(0);
    loadB(0);
    storeTiles();
    __syncthreads();

    constexpr int NKT = KDIM / BK;  // 16
#pragma unroll 1
    for (int kt = 0; kt < NKT; kt++) {
        if (kt < NKT - 1) { loadA(kt + 1); loadB(kt + 1); }

#pragma unroll
        for (int ks = 0; ks < 2; ks++) {      // two m16n8k16 steps per BK=32
            int kc = ks * 8;                  // pair-column offset
            uint32_t a[2][4], b[4][2];
#pragma unroll
            for (int mt = 0; mt < 2; mt++) {
                int base = (warpM + mt * 16 + (lane >> 2)) * SP + kc + (lane & 3);
                a[mt][0] = As[base];
                a[mt][1] = As[base + 8 * SP];
                a[mt][2] = As[base + 4];
                a[mt][3] = As[base + 8 * SP + 4];
            }
#pragma unroll
            for (int nt = 0; nt < 4; nt++) {
                int bb = (warpN + nt * 8 + (lane >> 2)) * SP + kc + (lane & 3);
                b[nt][0] = Bs[bb];
                b[nt][1] = Bs[bb + 4];
            }
#pragma unroll
            for (int mt = 0; mt < 2; mt++)
#pragma unroll
                for (int nt = 0; nt < 4; nt++)
                    mma_bf16(acc[mt][nt][0], acc[mt][nt][1], acc[mt][nt][2], acc[mt][nt][3],
                             a[mt][0], a[mt][1], a[mt][2], a[mt][3], b[nt][0], b[nt][1]);
        }
        __syncthreads();
        if (kt < NKT - 1) {
            storeTiles();
            __syncthreads();
        }
    }

    // epilogue
#pragma unroll
    for (int mt = 0; mt < 2; mt++) {
        int r0 = warpM + mt * 16 + (lane >> 2);
        size_t gr0 = (size_t)blockM + r0;
        size_t gr1 = gr0 + 8;
        int node0 = 0, node1 = 0;
        if (SCATTER) { node0 = ridx_s[r0]; node1 = ridx_s[r0 + 8]; }
#pragma unroll
        for (int nt = 0; nt < 4; nt++) {
            int col = blockN + warpN + nt * 8 + (lane & 3) * 2;
            float bv0 = bias[col], bv1 = bias[col + 1];
            float v0 = acc[mt][nt][0] + bv0;
            float v1 = acc[mt][nt][1] + bv1;
            float v2 = acc[mt][nt][2] + bv0;
            float v3 = acc[mt][nt][3] + bv1;
            if (RELU) {
                v0 = fmaxf(v0, 0.f); v1 = fmaxf(v1, 0.f);
                v2 = fmaxf(v2, 0.f); v3 = fmaxf(v3, 0.f);
            }
            if (SCATTER) {
                float* p0 = &g_agg[(size_t)node0 * 256 + col];
                float* p1 = &g_agg[(size_t)node1 * 256 + col];
                asm volatile("red.global.add.v2.f32 [%0], {%1, %2};"
                             :: "l"(p0), "f"(v0), "f"(v1) : "memory");
                asm volatile("red.global.add.v2.f32 [%0], {%1, %2};"
                             :: "l"(p1), "f"(v2), "f"(v3) : "memory");
            } else if (OUTBF) {
                __nv_bfloat16* C = (__nv_bfloat16*)Cv;
                *reinterpret_cast<__nv_bfloat162*>(C + gr0 * N + col) =
                    __floats2bfloat162_rn(v0, v1);
                *reinterpret_cast<__nv_bfloat162*>(C + gr1 * N + col) =
                    __floats2bfloat162_rn(v2, v3);
            } else {
                float* C = (float*)Cv;
                if (RESID) {
                    v0 += resid[gr0 * N + col];
                    v1 += resid[gr0 * N + col + 1];
                    v2 += resid[gr1 * N + col];
                    v3 += resid[gr1 * N + col + 1];
                }
                *reinterpret_cast<float2*>(C + gr0 * N + col) = make_float2(v0, v1);
                *reinterpret_cast<float2*>(C + gr1 * N + col) = make_float2(v2, v3);
            }
        }
    }
}

// ---------------- launch ----------------
extern "C" void kernel_launch(void* const* d_in, const int* in_sizes, int n_in,
                              void* d_out, int out_size) {
    const float* inputs   = (const float*)d_in[0];
    const float* rel_rec  = (const float*)d_in[1];
    const float* rel_send = (const float*)d_in[2];
    const float* msg_W1   = (const float*)d_in[3];
    const float* msg_b1   = (const float*)d_in[4];
    const float* msg_W2   = (const float*)d_in[5];
    const float* msg_b2   = (const float*)d_in[6];
    const float* out_W1   = (const float*)d_in[7];
    const float* out_b1   = (const float*)d_in[8];
    const float* out_W2   = (const float*)d_in[9];
    const float* out_b2   = (const float*)d_in[10];
    const float* out_W3   = (const float*)d_in[11];
    const float* out_b3   = (const float*)d_in[12];
    float* out = (float*)d_out;

    void* hid; void* agg; void* h1; void* h2;
    cudaGetSymbolAddress(&hid, g_hid);
    cudaGetSymbolAddress(&agg, g_agg);
    cudaGetSymbolAddress(&h1,  g_h1);
    cudaGetSymbolAddress(&h2,  g_h2);

    // 1) indices from one-hot (2 * 32768 warps)
    extract_idx_kernel<<<(2 * N_EDGES_C * 32) / 256, 256>>>(rel_rec, rel_send);
    // 2) zero aggregation buffer
    zero_agg_kernel<<<(N_NODES_C * 256 / 4) / 256, 256>>>();

    // 3) edge MLP layer 1: hid(bf16) = relu(concat(in[send], in[recv]) @ W1^T + b1)
    gemm_bf16_kernel<1, true, false, false, false, true>
        <<<dim3(N_EDGES_C / 128, 512 / 64), 256>>>(
            inputs, nullptr, msg_W1, msg_b1, nullptr, hid, 512);

    // 4) edge MLP layer 2 (bf16 A) + fused scatter-add into agg (f32)
    gemm_bf16_kernel<0, true, true, false, true, false>
        <<<dim3(N_EDGES_C / 128, 256 / 64), 256>>>(
            hid, nullptr, msg_W2, msg_b2, nullptr, agg, 256);

    // 5) node MLP layer 1: h1(bf16) = relu(concat(inputs, agg) @ outW1^T + b1)
    gemm_bf16_kernel<2, true, false, false, false, true>
        <<<dim3(N_NODES_C / 128, 512 / 64), 256>>>(
            inputs, (const float*)agg, out_W1, out_b1, nullptr, h1, 512);

    // 6) node MLP layer 2: h2(bf16) = relu(h1 @ outW2^T + b2)
    gemm_bf16_kernel<0, true, false, false, true, true>
        <<<dim3(N_NODES_C / 128, 512 / 64), 256>>>(
            h1, nullptr, out_W2, out_b2, nullptr, h2, 512);

    // 7) node MLP layer 3 + residual (f32 out)
    gemm_bf16_kernel<0, false, false, true, true, false>
        <<<dim3(N_NODES_C / 128, 256 / 64), 256>>>(
            h2, nullptr, out_W3, out_b3, inputs, out, 256);
}

// round 3
// speedup vs baseline: 1.4018x; 1.0972x over previous
#include <cuda_runtime.h>
#include <cuda_bf16.h>
#include <cstdint>

#define N_NODES_C 2048
#define N_EDGES_C 32768
#define KDIM 512

// ---------------- scratch (static device globals: allowed) ----------------
__device__ int            g_send_idx[N_EDGES_C];
__device__ int            g_recv_idx[N_EDGES_C];
__device__ __nv_bfloat16  g_hid[(size_t)N_EDGES_C * 512];  // edge hidden, bf16, 32MB
__device__ float          g_agg[N_NODES_C * 256];          // aggregated messages (f32 atomics)
__device__ __nv_bfloat16  g_h1[N_NODES_C * 512];
__device__ __nv_bfloat16  g_h2[N_NODES_C * 512];

// ---------------- index extraction from one-hot matrices ----------------
__global__ void extract_idx_kernel(const float* __restrict__ rel_rec,
                                   const float* __restrict__ rel_send) {
    int wg   = (blockIdx.x * blockDim.x + threadIdx.x) >> 5;
    int lane = threadIdx.x & 31;
    const float* mat;
    int* out;
    int e;
    if (wg < N_EDGES_C) { mat = rel_rec;  out = g_recv_idx; e = wg; }
    else                { mat = rel_send; out = g_send_idx; e = wg - N_EDGES_C; }

    const float4* row = reinterpret_cast<const float4*>(mat + (size_t)e * N_NODES_C);
    int found = 0;
#pragma unroll
    for (int i = 0; i < N_NODES_C / 128; i++) {
        float4 v = __ldcs(row + lane + i * 32);
        int base = (lane + i * 32) * 4;
        if (v.x != 0.f) found = base;
        if (v.y != 0.f) found = base + 1;
        if (v.z != 0.f) found = base + 2;
        if (v.w != 0.f) found = base + 3;
    }
#pragma unroll
    for (int o = 16; o > 0; o >>= 1)
        found = max(found, __shfl_xor_sync(0xffffffffu, found, o));
    if (lane == 0) out[e] = found;
}

// ---------------- zero the aggregation buffer ----------------
__global__ void zero_agg_kernel() {
    int i = blockIdx.x * blockDim.x + threadIdx.x;  // one float4 each
    reinterpret_cast<float4*>(g_agg)[i] = make_float4(0.f, 0.f, 0.f, 0.f);
}

// ---------------- bf16 / mma helpers ----------------
__device__ __forceinline__ uint32_t pk(float lo, float hi) {
    __nv_bfloat162 h = __floats2bfloat162_rn(lo, hi);
    return *reinterpret_cast<uint32_t*>(&h);
}
__device__ __forceinline__ void mma_bf16(float& d0, float& d1, float& d2, float& d3,
                                         uint32_t a0, uint32_t a1, uint32_t a2, uint32_t a3,
                                         uint32_t b0, uint32_t b1) {
    asm volatile(
        "mma.sync.aligned.m16n8k16.row.col.f32.bf16.bf16.f32 "
        "{%0,%1,%2,%3}, {%4,%5,%6,%7}, {%8,%9}, {%0,%1,%2,%3};"
        : "+f"(d0), "+f"(d1), "+f"(d2), "+f"(d3)
        : "r"(a0), "r"(a1), "r"(a2), "r"(a3), "r"(b0), "r"(b1));
}
__device__ __forceinline__ void ldsm4(uint32_t& r0, uint32_t& r1, uint32_t& r2, uint32_t& r3,
                                      uint32_t addr) {
    asm volatile("ldmatrix.sync.aligned.m8n8.x4.shared.b16 {%0,%1,%2,%3}, [%4];"
                 : "=r"(r0), "=r"(r1), "=r"(r2), "=r"(r3) : "r"(addr));
}

// ---------------- generic fused GEMM: C = act(A @ W^T + b) ----------------
// AMODE 0: A0 is [M, 512] plain (f32 if !ABF, bf16 if ABF)
// AMODE 1: row r = concat(inputs[send[r]](256), inputs[recv[r]](256)); A0 = inputs (f32)
// AMODE 2: row r = concat(A0[r](256), A1[r](256)) both f32
// SCATTER: red.add into g_agg[recv_idx[row]] instead of store (N must be 256)
// RESID:   add resid[row*N+col] before store (no relu)
// OUTBF:   store C as bf16
template <int AMODE, bool RELU, bool SCATTER, bool RESID, bool ABF, bool OUTBF>
__global__ __launch_bounds__(256, 2) void gemm_bf16_kernel(
    const void* __restrict__ A0v, const float* __restrict__ A1,
    const float* __restrict__ W, const float* __restrict__ bias,
    const float* __restrict__ resid, void* __restrict__ Cv, int N) {

    constexpr int BM = 128, BN = 64, BK = 32;
    constexpr int SP = 20;  // uint32 pairs per row: 16 data + 4 pad -> conflict-free LDSM
    __shared__ uint32_t As[2][BM * SP];
    __shared__ uint32_t Bs[2][BN * SP];
    __shared__ int      sidx_s[BM];
    __shared__ int      ridx_s[BM];

    const int tid    = threadIdx.x;
    const int lane   = tid & 31;
    const int warp   = tid >> 5;
    const int warpM  = (warp & 3) * 32;
    const int warpN  = (warp >> 2) * 32;
    const int blockM = blockIdx.x * BM;
    const int blockN = blockIdx.y * BN;

    const uint32_t as0 = (uint32_t)__cvta_generic_to_shared(&As[0][0]);
    const uint32_t bs0 = (uint32_t)__cvta_generic_to_shared(&Bs[0][0]);

    if (AMODE == 1 || SCATTER) {
        if (tid < BM) {
            if (AMODE == 1) sidx_s[tid] = g_send_idx[blockM + tid];
            ridx_s[tid] = g_recv_idx[blockM + tid];
        }
        __syncthreads();
    }

    float acc[2][4][4];
#pragma unroll
    for (int mt = 0; mt < 2; mt++)
#pragma unroll
        for (int nt = 0; nt < 4; nt++)
#pragma unroll
            for (int j = 0; j < 4; j++) acc[mt][nt][j] = 0.f;

    float4 aF[4];
    uint2  aH[4];
    float4 bF[2];

    auto loadA = [&](int kt) {
#pragma unroll
        for (int i = 0; i < 4; i++) {
            int f   = tid + i * 256;
            int row = f >> 3;
            int c4  = f & 7;
            int kg  = kt * BK + c4 * 4;
            if (ABF) {
                const __nv_bfloat16* p =
                    (const __nv_bfloat16*)A0v + (size_t)(blockM + row) * KDIM + kg;
                aH[i] = *reinterpret_cast<const uint2*>(p);
            } else {
                const float* A0 = (const float*)A0v;
                const float* p;
                if (AMODE == 0) {
                    p = A0 + (size_t)(blockM + row) * KDIM + kg;
                } else if (AMODE == 1) {
                    int node = (kg < 256) ? sidx_s[row] : ridx_s[row];
                    p = A0 + (size_t)node * 256 + (kg & 255);
                } else {
                    p = (kg < 256) ? (A0 + (size_t)(blockM + row) * 256 + kg)
                                   : (A1 + (size_t)(blockM + row) * 256 + (kg - 256));
                }
                aF[i] = *reinterpret_cast<const float4*>(p);
            }
        }
    };
    auto loadB = [&](int kt) {
#pragma unroll
        for (int i = 0; i < 2; i++) {
            int f  = tid + i * 256;
            int n  = f >> 3;
            int c4 = f & 7;
            bF[i] = *reinterpret_cast<const float4*>(
                W + (size_t)(blockN + n) * KDIM + kt * BK + c4 * 4);
        }
    };
    auto storeTiles = [&](int stage) {
#pragma unroll
        for (int i = 0; i < 4; i++) {
            int f = tid + i * 256, row = f >> 3, c4 = f & 7;
            uint32_t* dst = &As[stage][row * SP + c4 * 2];
            if (ABF) {
                dst[0] = aH[i].x;
                dst[1] = aH[i].y;
            } else {
                dst[0] = pk(aF[i].x, aF[i].y);
                dst[1] = pk(aF[i].z, aF[i].w);
            }
        }
#pragma unroll
        for (int i = 0; i < 2; i++) {
            int f = tid + i * 256, n = f >> 3, c4 = f & 7;
            uint32_t* dst = &Bs[stage][n * SP + c4 * 2];
            dst[0] = pk(bF[i].x, bF[i].y);
            dst[1] = pk(bF[i].z, bF[i].w);
        }
    };

    loadA(0);
    loadB(0);
    storeTiles(0);
    __syncthreads();

    // LDSM lane addressing (bytes), constant per thread:
    //  A: row = warpM + mt*16 + (lane&15), word off = kc + (lane>=16 ? 4 : 0)
    //  B: row = warpN + ntp*16 + (lane&7) + (lane&16 ? 8 : 0), word off = kc + (lane&8 ? 4 : 0)
    const uint32_t aRowOff = (uint32_t)((lane & 15) * SP + ((lane >> 4) << 2)) * 4u;
    const uint32_t bRowOff = (uint32_t)(((lane & 7) + ((lane & 16) >> 1)) * SP +
                                        ((lane & 8) >> 1)) * 4u;

    constexpr int NKT = KDIM / BK;  // 16
#pragma unroll 1
    for (int kt = 0; kt < NKT; kt++) {
        const int cur = kt & 1;
        if (kt < NKT - 1) { loadA(kt + 1); loadB(kt + 1); }

        const uint32_t asb = as0 + (uint32_t)cur * (BM * SP * 4) + aRowOff;
        const uint32_t bsb = bs0 + (uint32_t)cur * (BN * SP * 4) + bRowOff;

#pragma unroll
        for (int ks = 0; ks < 2; ks++) {      // two m16n8k16 steps per BK=32
            const uint32_t kcb = (uint32_t)(ks * 8 * 4);
            uint32_t a[2][4], b[4][2];
#pragma unroll
            for (int mt = 0; mt < 2; mt++)
                ldsm4(a[mt][0], a[mt][1], a[mt][2], a[mt][3],
                      asb + (uint32_t)((warpM + mt * 16) * SP * 4) + kcb);
#pragma unroll
            for (int ntp = 0; ntp < 2; ntp++)
                ldsm4(b[2 * ntp][0], b[2 * ntp][1], b[2 * ntp + 1][0], b[2 * ntp + 1][1],
                      bsb + (uint32_t)((warpN + ntp * 16) * SP * 4) + kcb);
#pragma unroll
            for (int mt = 0; mt < 2; mt++)
#pragma unroll
                for (int nt = 0; nt < 4; nt++)
                    mma_bf16(acc[mt][nt][0], acc[mt][nt][1], acc[mt][nt][2], acc[mt][nt][3],
                             a[mt][0], a[mt][1], a[mt][2], a[mt][3], b[nt][0], b[nt][1]);
        }

        if (kt < NKT - 1) {
            storeTiles((kt + 1) & 1);
            __syncthreads();
        }
    }

    // epilogue
#pragma unroll
    for (int mt = 0; mt < 2; mt++) {
        int r0 = warpM + mt * 16 + (lane >> 2);
        size_t gr0 = (size_t)blockM + r0;
        size_t gr1 = gr0 + 8;
        int node0 = 0, node1 = 0;
        if (SCATTER) { node0 = ridx_s[r0]; node1 = ridx_s[r0 + 8]; }
#pragma unroll
        for (int nt = 0; nt < 4; nt++) {
            int col = blockN + warpN + nt * 8 + (lane & 3) * 2;
            float bv0 = bias[col], bv1 = bias[col + 1];
            float v0 = acc[mt][nt][0] + bv0;
            float v1 = acc[mt][nt][1] + bv1;
            float v2 = acc[mt][nt][2] + bv0;
            float v3 = acc[mt][nt][3] + bv1;
            if (RELU) {
                v0 = fmaxf(v0, 0.f); v1 = fmaxf(v1, 0.f);
                v2 = fmaxf(v2, 0.f); v3 = fmaxf(v3, 0.f);
            }
            if (SCATTER) {
                float* p0 = &g_agg[(size_t)node0 * 256 + col];
                float* p1 = &g_agg[(size_t)node1 * 256 + col];
                asm volatile("red.global.add.v2.f32 [%0], {%1, %2};"
                             :: "l"(p0), "f"(v0), "f"(v1) : "memory");
                asm volatile("red.global.add.v2.f32 [%0], {%1, %2};"
                             :: "l"(p1), "f"(v2), "f"(v3) : "memory");
            } else if (OUTBF) {
                __nv_bfloat16* C = (__nv_bfloat16*)Cv;
                *reinterpret_cast<__nv_bfloat162*>(C + gr0 * N + col) =
                    __floats2bfloat162_rn(v0, v1);
                *reinterpret_cast<__nv_bfloat162*>(C + gr1 * N + col) =
                    __floats2bfloat162_rn(v2, v3);
            } else {
                float* C = (float*)Cv;
                if (RESID) {
                    v0 += resid[gr0 * N + col];
                    v1 += resid[gr0 * N + col + 1];
                    v2 += resid[gr1 * N + col];
                    v3 += resid[gr1 * N + col + 1];
                }
                *reinterpret_cast<float2*>(C + gr0 * N + col) = make_float2(v0, v1);
                *reinterpret_cast<float2*>(C + gr1 * N + col) = make_float2(v2, v3);
            }
        }
    }
}

// ---------------- launch ----------------
extern "C" void kernel_launch(void* const* d_in, const int* in_sizes, int n_in,
                              void* d_out, int out_size) {
    const float* inputs   = (const float*)d_in[0];
    const float* rel_rec  = (const float*)d_in[1];
    const float* rel_send = (const float*)d_in[2];
    const float* msg_W1   = (const float*)d_in[3];
    const float* msg_b1   = (const float*)d_in[4];
    const float* msg_W2   = (const float*)d_in[5];
    const float* msg_b2   = (const float*)d_in[6];
    const float* out_W1   = (const float*)d_in[7];
    const float* out_b1   = (const float*)d_in[8];
    const float* out_W2   = (const float*)d_in[9];
    const float* out_b2   = (const float*)d_in[10];
    const float* out_W3   = (const float*)d_in[11];
    const float* out_b3   = (const float*)d_in[12];
    float* out = (float*)d_out;

    void* hid; void* agg; void* h1; void* h2;
    cudaGetSymbolAddress(&hid, g_hid);
    cudaGetSymbolAddress(&agg, g_agg);
    cudaGetSymbolAddress(&h1,  g_h1);
    cudaGetSymbolAddress(&h2,  g_h2);

    // 1) indices from one-hot (2 * 32768 warps)
    extract_idx_kernel<<<(2 * N_EDGES_C * 32) / 256, 256>>>(rel_rec, rel_send);
    // 2) zero aggregation buffer
    zero_agg_kernel<<<(N_NODES_C * 256 / 4) / 256, 256>>>();

    // 3) edge MLP layer 1: hid(bf16) = relu(concat(in[send], in[recv]) @ W1^T + b1)
    gemm_bf16_kernel<1, true, false, false, false, true>
        <<<dim3(N_EDGES_C / 128, 512 / 64), 256>>>(
            inputs, nullptr, msg_W1, msg_b1, nullptr, hid, 512);

    // 4) edge MLP layer 2 (bf16 A) + fused scatter-add into agg (f32)
    gemm_bf16_kernel<0, true, true, false, true, false>
        <<<dim3(N_EDGES_C / 128, 256 / 64), 256>>>(
            hid, nullptr, msg_W2, msg_b2, nullptr, agg, 256);

    // 5) node MLP layer 1: h1(bf16) = relu(concat(inputs, agg) @ outW1^T + b1)
    gemm_bf16_kernel<2, true, false, false, false, true>
        <<<dim3(N_NODES_C / 128, 512 / 64), 256>>>(
            inputs, (const float*)agg, out_W1, out_b1, nullptr, h1, 512);

    // 6) node MLP layer 2: h2(bf16) = relu(h1 @ outW2^T + b2)
    gemm_bf16_kernel<0, true, false, false, true, true>
        <<<dim3(N_NODES_C / 128, 512 / 64), 256>>>(
            h1, nullptr, out_W2, out_b2, nullptr, h2, 512);

    // 7) node MLP layer 3 + residual (f32 out)
    gemm_bf16_kernel<0, false, false, true, true, false>
        <<<dim3(N_NODES_C / 128, 256 / 64), 256>>>(
            h2, nullptr, out_W3, out_b3, inputs, out, 256);
}

// round 5
// speedup vs baseline: 1.6259x; 1.1598x over previous
#include <cuda_runtime.h>
#include <cuda_bf16.h>
#include <cstdint>

#define N_NODES_C 2048
#define N_EDGES_C 32768

// ---------------- scratch (static device globals: allowed) ----------------
__device__ int            g_send_idx[N_EDGES_C];
__device__ int            g_recv_idx[N_EDGES_C];
__device__ __nv_bfloat16  g_pre[(size_t)N_EDGES_C * 512];  // gathered pre_msg bf16, 32MB
__device__ __nv_bfloat16  g_hid[(size_t)N_EDGES_C * 512];  // edge hidden bf16, 32MB
__device__ float          g_agg[N_NODES_C * 256];          // aggregated messages (f32 atomics)
__device__ __nv_bfloat16  g_aug[N_NODES_C * 512];          // concat(inputs, agg) bf16
__device__ __nv_bfloat16  g_h1[(size_t)N_NODES_C * 512];
__device__ __nv_bfloat16  g_h2[(size_t)N_NODES_C * 512];
__device__ __nv_bfloat16  g_wbf[1048576];                  // all 5 weight mats, bf16

// weight offsets inside g_wbf
#define W1_OFF 0         // msg_W1 512x512
#define W2_OFF 262144    // msg_W2 256x512
#define W3_OFF 393216    // out_W1 512x512
#define W4_OFF 655360    // out_W2 512x512
#define W5_OFF 917504    // out_W3 256x512

// ---------------- helpers ----------------
__device__ __forceinline__ uint32_t pk(float lo, float hi) {
    __nv_bfloat162 h = __floats2bfloat162_rn(lo, hi);
    return *reinterpret_cast<uint32_t*>(&h);
}
__device__ __forceinline__ void mma_bf16(float& d0, float& d1, float& d2, float& d3,
                                         uint32_t a0, uint32_t a1, uint32_t a2, uint32_t a3,
                                         uint32_t b0, uint32_t b1) {
    asm volatile(
        "mma.sync.aligned.m16n8k16.row.col.f32.bf16.bf16.f32 "
        "{%0,%1,%2,%3}, {%4,%5,%6,%7}, {%8,%9}, {%0,%1,%2,%3};"
        : "+f"(d0), "+f"(d1), "+f"(d2), "+f"(d3)
        : "r"(a0), "r"(a1), "r"(a2), "r"(a3), "r"(b0), "r"(b1));
}
__device__ __forceinline__ void ldsm4(uint32_t& r0, uint32_t& r1, uint32_t& r2, uint32_t& r3,
                                      uint32_t addr) {
    asm volatile("ldmatrix.sync.aligned.m8n8.x4.shared.b16 {%0,%1,%2,%3}, [%4];"
                 : "=r"(r0), "=r"(r1), "=r"(r2), "=r"(r3) : "r"(addr));
}
__device__ __forceinline__ void cp16(uint32_t dst, const void* src) {
    asm volatile("cp.async.cg.shared.global [%0], [%1], 16;" :: "r"(dst), "l"(src));
}
#define CP_COMMIT() asm volatile("cp.async.commit_group;" ::: "memory")
#define CP_WAIT1()  asm volatile("cp.async.wait_group 1;" ::: "memory")

// ---------------- index extraction from one-hot matrices ----------------
__global__ void extract_idx_kernel(const float* __restrict__ rel_rec,
                                   const float* __restrict__ rel_send) {
    int wg   = (blockIdx.x * blockDim.x + threadIdx.x) >> 5;
    int lane = threadIdx.x & 31;
    const float* mat;
    int* out;
    int e;
    if (wg < N_EDGES_C) { mat = rel_rec;  out = g_recv_idx; e = wg; }
    else                { mat = rel_send; out = g_send_idx; e = wg - N_EDGES_C; }

    const float4* row = reinterpret_cast<const float4*>(mat + (size_t)e * N_NODES_C);
    int found = 0;
#pragma unroll
    for (int i = 0; i < N_NODES_C / 128; i++) {
        float4 v = __ldcs(row + lane + i * 32);
        int base = (lane + i * 32) * 4;
        if (v.x != 0.f) found = base;
        if (v.y != 0.f) found = base + 1;
        if (v.z != 0.f) found = base + 2;
        if (v.w != 0.f) found = base + 3;
    }
#pragma unroll
    for (int o = 16; o > 0; o >>= 1)
        found = max(found, __shfl_xor_sync(0xffffffffu, found, o));
    if (lane == 0) out[e] = found;
}

// ---------------- zero the aggregation buffer ----------------
__global__ void zero_agg_kernel() {
    int i = blockIdx.x * blockDim.x + threadIdx.x;
    reinterpret_cast<float4*>(g_agg)[i] = make_float4(0.f, 0.f, 0.f, 0.f);
}

// ---------------- convert all weights f32 -> bf16 into g_wbf ----------------
__global__ void convert_weights_kernel(const float* __restrict__ w1, const float* __restrict__ w2,
                                       const float* __restrict__ w3, const float* __restrict__ w4,
                                       const float* __restrict__ w5) {
    int t = (blockIdx.x * blockDim.x + threadIdx.x) * 4;
    const float* src;
    int off;
    if      (t < W2_OFF) { src = w1; off = t; }
    else if (t < W3_OFF) { src = w2; off = t - W2_OFF; }
    else if (t < W4_OFF) { src = w3; off = t - W3_OFF; }
    else if (t < W5_OFF) { src = w4; off = t - W4_OFF; }
    else                 { src = w5; off = t - W5_OFF; }
    float4 v = *reinterpret_cast<const float4*>(src + off);
    uint2 o;
    o.x = pk(v.x, v.y);
    o.y = pk(v.z, v.w);
    *reinterpret_cast<uint2*>(g_wbf + t) = o;
}

// ---------------- gather pre_msg = concat(inputs[send], inputs[recv]) -> bf16 ----------------
__global__ void gather_kernel(const float* __restrict__ inputs) {
    int gid = blockIdx.x * blockDim.x + threadIdx.x;   // one thread = 8 bf16
    int e   = gid >> 6;
    int c8  = (gid & 63) << 3;   // 0..504
    int node = (c8 < 256) ? g_send_idx[e] : g_recv_idx[e];
    const float4* src = reinterpret_cast<const float4*>(inputs + (size_t)node * 256 + (c8 & 255));
    float4 v0 = src[0], v1 = src[1];
    uint4 o;
    o.x = pk(v0.x, v0.y); o.y = pk(v0.z, v0.w);
    o.z = pk(v1.x, v1.y); o.w = pk(v1.z, v1.w);
    *reinterpret_cast<uint4*>(g_pre + (size_t)e * 512 + c8) = o;
}

// ---------------- aug = concat(inputs, agg) -> bf16 ----------------
__global__ void concat_aug_kernel(const float* __restrict__ inputs) {
    int t = (blockIdx.x * blockDim.x + threadIdx.x) * 4;   // over 2048*512
    int row = t >> 9, col = t & 511;
    float4 v = (col < 256)
        ? *reinterpret_cast<const float4*>(inputs + (size_t)row * 256 + col)
        : *reinterpret_cast<const float4*>(g_agg + (size_t)row * 256 + (col - 256));
    uint2 o;
    o.x = pk(v.x, v.y);
    o.y = pk(v.z, v.w);
    *reinterpret_cast<uint2*>(g_aug + t) = o;
}

// ---------------- all-bf16 GEMM with cp.async 3-stage pipeline ----------------
// C = act(A @ W^T + b); A [M,512] bf16, W [N,512] bf16.
// SCATTER: red.add rows into g_agg[recv_idx[row]] (Ntot==256).
// RESID:   f32 out, += resid, no relu.  OUTBF: bf16 out.
template <bool RELU, bool SCATTER, bool RESID, bool OUTBF>
__global__ __launch_bounds__(256, 3) void gemm_cp_kernel(
    const __nv_bfloat16* __restrict__ A, const __nv_bfloat16* __restrict__ Wm,
    const float* __restrict__ bias, const float* __restrict__ resid,
    void* __restrict__ Cv, int Ntot) {

    constexpr int BM = 128, BN = 64, BK = 32;
    constexpr int SP = 20;                     // uint32 per row: 16 data + 4 pad
    constexpr int A_U32 = BM * SP;             // 2560
    constexpr int B_U32 = BN * SP;             // 1280
    constexpr int STG_U32 = A_U32 + B_U32;     // 3840 (15360B)
    constexpr int STAGES = 3;
    __shared__ uint32_t sm[STAGES * STG_U32];
    __shared__ int ridx_s[BM];

    const int tid    = threadIdx.x;
    const int lane   = tid & 31;
    const int warp   = tid >> 5;
    const int warpM  = (warp & 3) * 32;
    const int warpN  = (warp >> 2) * 32;
    const int blockM = blockIdx.x * BM;
    const int blockN = blockIdx.y * BN;
    const uint32_t smBase = (uint32_t)__cvta_generic_to_shared(sm);

    if (SCATTER && tid < BM) ridx_s[tid] = g_recv_idx[blockM + tid];

    float acc[2][4][4];
#pragma unroll
    for (int mt = 0; mt < 2; mt++)
#pragma unroll
        for (int nt = 0; nt < 4; nt++)
#pragma unroll
            for (int j = 0; j < 4; j++) acc[mt][nt][j] = 0.f;

    // per-thread load slots: A = 2 x 16B chunks, B = 1 x 16B chunk
    const int ar0 = tid >> 2, ac = tid & 3;            // A rows tid>>2 and +64
    const int br  = tid >> 2;                          // B row 0..63
    auto issue = [&](int kt, int stage) {
        uint32_t sa = smBase + (uint32_t)stage * STG_U32 * 4;
        cp16(sa + (uint32_t)(ar0 * SP + ac * 4) * 4,
             A + (size_t)(blockM + ar0) * 512 + kt * BK + ac * 8);
        cp16(sa + (uint32_t)((ar0 + 64) * SP + ac * 4) * 4,
             A + (size_t)(blockM + ar0 + 64) * 512 + kt * BK + ac * 8);
        cp16(sa + (uint32_t)(A_U32 + br * SP + ac * 4) * 4,
             Wm + (size_t)(blockN + br) * 512 + kt * BK + ac * 8);
    };

    issue(0, 0); CP_COMMIT();
    issue(1, 1); CP_COMMIT();

    // LDSM lane addressing (bytes), constant per thread
    const uint32_t aRowOff = (uint32_t)((lane & 15) * SP + ((lane >> 4) << 2)) * 4u;
    const uint32_t bRowOff = (uint32_t)(((lane & 7) + ((lane & 16) >> 1)) * SP +
                                        ((lane & 8) >> 1)) * 4u;

    constexpr int NKT = 512 / BK;  // 16
#pragma unroll 1
    for (int kt = 0; kt < NKT; kt++) {
        CP_WAIT1();
        __syncthreads();
        if (kt + 2 < NKT) issue(kt + 2, (kt + 2) % STAGES);
        CP_COMMIT();

        const uint32_t sbase = smBase + (uint32_t)(kt % STAGES) * STG_U32 * 4;
        const uint32_t asb = sbase + aRowOff;
        const uint32_t bsb = sbase + A_U32 * 4 + bRowOff;

#pragma unroll
        for (int ks = 0; ks < 2; ks++) {
            const uint32_t kcb = (uint32_t)(ks * 8 * 4);
            uint32_t a[2][4], b[4][2];
#pragma unroll
            for (int mt = 0; mt < 2; mt++)
                ldsm4(a[mt][0], a[mt][1], a[mt][2], a[mt][3],
                      asb + (uint32_t)((warpM + mt * 16) * SP * 4) + kcb);
#pragma unroll
            for (int ntp = 0; ntp < 2; ntp++)
                ldsm4(b[2 * ntp][0], b[2 * ntp][1], b[2 * ntp + 1][0], b[2 * ntp + 1][1],
                      bsb + (uint32_t)((warpN + ntp * 16) * SP * 4) + kcb);
#pragma unroll
            for (int mt = 0; mt < 2; mt++)
#pragma unroll
                for (int nt = 0; nt < 4; nt++)
                    mma_bf16(acc[mt][nt][0], acc[mt][nt][1], acc[mt][nt][2], acc[mt][nt][3],
                             a[mt][0], a[mt][1], a[mt][2], a[mt][3], b[nt][0], b[nt][1]);
        }
    }

    // epilogue
#pragma unroll
    for (int mt = 0; mt < 2; mt++) {
        int r0 = warpM + mt * 16 + (lane >> 2);
        size_t gr0 = (size_t)blockM + r0;
        size_t gr1 = gr0 + 8;
        int node0 = 0, node1 = 0;
        if (SCATTER) { node0 = ridx_s[r0]; node1 = ridx_s[r0 + 8]; }
#pragma unroll
        for (int nt = 0; nt < 4; nt++) {
            int col = blockN + warpN + nt * 8 + (lane & 3) * 2;
            float bv0 = bias[col], bv1 = bias[col + 1];
            float v0 = acc[mt][nt][0] + bv0;
            float v1 = acc[mt][nt][1] + bv1;
            float v2 = acc[mt][nt][2] + bv0;
            float v3 = acc[mt][nt][3] + bv1;
            if (RELU) {
                v0 = fmaxf(v0, 0.f); v1 = fmaxf(v1, 0.f);
                v2 = fmaxf(v2, 0.f); v3 = fmaxf(v3, 0.f);
            }
            if (SCATTER) {
                float* p0 = &g_agg[(size_t)node0 * 256 + col];
                float* p1 = &g_agg[(size_t)node1 * 256 + col];
                asm volatile("red.global.add.v2.f32 [%0], {%1, %2};"
                             :: "l"(p0), "f"(v0), "f"(v1) : "memory");
                asm volatile("red.global.add.v2.f32 [%0], {%1, %2};"
                             :: "l"(p1), "f"(v2), "f"(v3) : "memory");
            } else if (RESID) {
                v0 += resid[gr0 * Ntot + col];
                v1 += resid[gr0 * Ntot + col + 1];
                v2 += resid[gr1 * Ntot + col];
                v3 += resid[gr1 * Ntot + col + 1];
                *reinterpret_cast<float2*>((float*)Cv + gr0 * Ntot + col) = make_float2(v0, v1);
                *reinterpret_cast<float2*>((float*)Cv + gr1 * Ntot + col) = make_float2(v2, v3);
            } else if (OUTBF) {
                __nv_bfloat16* C = (__nv_bfloat16*)Cv;
                *reinterpret_cast<__nv_bfloat162*>(C + gr0 * Ntot + col) =
                    __floats2bfloat162_rn(v0, v1);
                *reinterpret_cast<__nv_bfloat162*>(C + gr1 * Ntot + col) =
                    __floats2bfloat162_rn(v2, v3);
            }
        }
    }
}

// ---------------- launch ----------------
extern "C" void kernel_launch(void* const* d_in, const int* in_sizes, int n_in,
                              void* d_out, int out_size) {
    const float* inputs   = (const float*)d_in[0];
    const float* rel_rec  = (const float*)d_in[1];
    const float* rel_send = (const float*)d_in[2];
    const float* msg_W1   = (const float*)d_in[3];
    const float* msg_b1   = (const float*)d_in[4];
    const float* msg_W2   = (const float*)d_in[5];
    const float* msg_b2   = (const float*)d_in[6];
    const float* out_W1   = (const float*)d_in[7];
    const float* out_b1   = (const float*)d_in[8];
    const float* out_W2   = (const float*)d_in[9];
    const float* out_b2   = (const float*)d_in[10];
    const float* out_W3   = (const float*)d_in[11];
    const float* out_b3   = (const float*)d_in[12];
    float* out = (float*)d_out;

    void *pre, *hid, *aug, *h1, *h2, *wbf;
    cudaGetSymbolAddress(&pre, g_pre);
    cudaGetSymbolAddress(&hid, g_hid);
    cudaGetSymbolAddress(&aug, g_aug);
    cudaGetSymbolAddress(&h1,  g_h1);
    cudaGetSymbolAddress(&h2,  g_h2);
    cudaGetSymbolAddress(&wbf, g_wbf);
    const __nv_bfloat16* wb = (const __nv_bfloat16*)wbf;

    // 1) indices from one-hot
    extract_idx_kernel<<<(2 * N_EDGES_C * 32) / 256, 256>>>(rel_rec, rel_send);
    // 2) zero aggregation buffer
    zero_agg_kernel<<<(N_NODES_C * 256 / 4) / 256, 256>>>();
    // 3) weights -> bf16
    convert_weights_kernel<<<1048576 / 4 / 256, 256>>>(msg_W1, msg_W2, out_W1, out_W2, out_W3);
    // 4) gather pre_msg bf16
    gather_kernel<<<(N_EDGES_C * 64) / 256, 256>>>(inputs);

    // 5) edge MLP layer 1: hid = relu(pre @ W1^T + b1)   [32768,512]
    gemm_cp_kernel<true, false, false, true>
        <<<dim3(N_EDGES_C / 128, 8), 256>>>(
            (const __nv_bfloat16*)pre, wb + W1_OFF, msg_b1, nullptr, hid, 512);

    // 6) edge MLP layer 2 + scatter-add into agg          [32768,256]
    gemm_cp_kernel<true, true, false, false>
        <<<dim3(N_EDGES_C / 128, 4), 256>>>(
            (const __nv_bfloat16*)hid, wb + W2_OFF, msg_b2, nullptr, nullptr, 256);

    // 7) aug = concat(inputs, agg) bf16
    concat_aug_kernel<<<(N_NODES_C * 512 / 4) / 256, 256>>>(inputs);

    // 8) node MLP layer 1: h1 = relu(aug @ outW1^T + b1)  [2048,512]
    gemm_cp_kernel<true, false, false, true>
        <<<dim3(N_NODES_C / 128, 8), 256>>>(
            (const __nv_bfloat16*)aug, wb + W3_OFF, out_b1, nullptr, h1, 512);

    // 9) node MLP layer 2: h2 = relu(h1 @ outW2^T + b2)   [2048,512]
    gemm_cp_kernel<true, false, false, true>
        <<<dim3(N_NODES_C / 128, 8), 256>>>(
            (const __nv_bfloat16*)h1, wb + W4_OFF, out_b2, nullptr, h2, 512);

    // 10) node MLP layer 3 + residual (f32 out)           [2048,256]
    gemm_cp_kernel<false, false, true, false>
        <<<dim3(N_NODES_C / 128, 4), 256>>>(
            (const __nv_bfloat16*)h2, wb + W5_OFF, out_b3, inputs, out, 256);
}

// round 6
// speedup vs baseline: 1.7805x; 1.0951x over previous
#include <cuda_runtime.h>
#include <cuda_bf16.h>
#include <cstdint>

#define N_NODES_C 2048
#define N_EDGES_C 32768

// ---------------- scratch (static device globals: allowed) ----------------
__device__ int            g_send_idx[N_EDGES_C];
__device__ int            g_recv_idx[N_EDGES_C];
__device__ __nv_bfloat16  g_pre[(size_t)N_EDGES_C * 512];  // gathered pre_msg bf16, 32MB
__device__ __nv_bfloat16  g_hid[(size_t)N_EDGES_C * 512];  // edge hidden bf16, 32MB
__device__ float          g_agg[N_NODES_C * 256];          // aggregated messages (f32 atomics)
__device__ __nv_bfloat16  g_aug[N_NODES_C * 512];          // concat(inputs, agg) bf16
__device__ __nv_bfloat16  g_h1[(size_t)N_NODES_C * 512];
__device__ __nv_bfloat16  g_h2[(size_t)N_NODES_C * 512];
__device__ __nv_bfloat16  g_wbf[1048576];                  // all 5 weight mats, bf16

// weight offsets inside g_wbf
#define W1_OFF 0         // msg_W1 512x512
#define W2_OFF 262144    // msg_W2 256x512
#define W3_OFF 393216    // out_W1 512x512
#define W4_OFF 655360    // out_W2 512x512
#define W5_OFF 917504    // out_W3 256x512

// ---------------- helpers ----------------
__device__ __forceinline__ uint32_t pk(float lo, float hi) {
    __nv_bfloat162 h = __floats2bfloat162_rn(lo, hi);
    return *reinterpret_cast<uint32_t*>(&h);
}
__device__ __forceinline__ void mma_bf16(float& d0, float& d1, float& d2, float& d3,
                                         uint32_t a0, uint32_t a1, uint32_t a2, uint32_t a3,
                                         uint32_t b0, uint32_t b1) {
    asm volatile(
        "mma.sync.aligned.m16n8k16.row.col.f32.bf16.bf16.f32 "
        "{%0,%1,%2,%3}, {%4,%5,%6,%7}, {%8,%9}, {%0,%1,%2,%3};"
        : "+f"(d0), "+f"(d1), "+f"(d2), "+f"(d3)
        : "r"(a0), "r"(a1), "r"(a2), "r"(a3), "r"(b0), "r"(b1));
}
__device__ __forceinline__ void ldsm4(uint32_t& r0, uint32_t& r1, uint32_t& r2, uint32_t& r3,
                                      uint32_t addr) {
    asm volatile("ldmatrix.sync.aligned.m8n8.x4.shared.b16 {%0,%1,%2,%3}, [%4];"
                 : "=r"(r0), "=r"(r1), "=r"(r2), "=r"(r3) : "r"(addr));
}
__device__ __forceinline__ void cp16(uint32_t dst, const void* src) {
    asm volatile("cp.async.cg.shared.global [%0], [%1], 16;" :: "r"(dst), "l"(src));
}
#define CP_COMMIT() asm volatile("cp.async.commit_group;" ::: "memory")
#define CP_WAIT1()  asm volatile("cp.async.wait_group 1;" ::: "memory")

// ---------------- index extraction: ballot early-exit (expected 53% traffic) ----------------
__global__ void extract_idx_kernel(const float* __restrict__ rel_rec,
                                   const float* __restrict__ rel_send) {
    int wg   = (blockIdx.x * blockDim.x + threadIdx.x) >> 5;
    int lane = threadIdx.x & 31;
    const float* mat;
    int* out;
    int e;
    if (wg < N_EDGES_C) { mat = rel_rec;  out = g_recv_idx; e = wg; }
    else                { mat = rel_send; out = g_send_idx; e = wg - N_EDGES_C; }

    const float4* p = reinterpret_cast<const float4*>(mat + (size_t)e * N_NODES_C) + lane;
    float4 v = __ldcs(p);                       // chunk 0
#pragma unroll 1
    for (int i = 0; i < 16; i++) {
        float4 nv;
        if (i < 15) nv = __ldcs(p + (i + 1) * 32);   // prefetch next chunk (MLP=2)
        int base = (lane + i * 32) * 4;
        int f = -1;
        if (v.x != 0.f) f = base;
        if (v.y != 0.f) f = base + 1;
        if (v.z != 0.f) f = base + 2;
        if (v.w != 0.f) f = base + 3;
        if (__ballot_sync(0xffffffffu, f >= 0)) {
            if (f >= 0) out[e] = f;             // exactly one nonzero per row
            break;
        }
        v = nv;
    }
}

// ---------------- zero the aggregation buffer ----------------
__global__ void zero_agg_kernel() {
    int i = blockIdx.x * blockDim.x + threadIdx.x;
    reinterpret_cast<float4*>(g_agg)[i] = make_float4(0.f, 0.f, 0.f, 0.f);
}

// ---------------- convert all weights f32 -> bf16 into g_wbf ----------------
__global__ void convert_weights_kernel(const float* __restrict__ w1, const float* __restrict__ w2,
                                       const float* __restrict__ w3, const float* __restrict__ w4,
                                       const float* __restrict__ w5) {
    int t = (blockIdx.x * blockDim.x + threadIdx.x) * 4;
    const float* src;
    int off;
    if      (t < W2_OFF) { src = w1; off = t; }
    else if (t < W3_OFF) { src = w2; off = t - W2_OFF; }
    else if (t < W4_OFF) { src = w3; off = t - W3_OFF; }
    else if (t < W5_OFF) { src = w4; off = t - W4_OFF; }
    else                 { src = w5; off = t - W5_OFF; }
    float4 v = *reinterpret_cast<const float4*>(src + off);
    uint2 o;
    o.x = pk(v.x, v.y);
    o.y = pk(v.z, v.w);
    *reinterpret_cast<uint2*>(g_wbf + t) = o;
}

// ---------------- gather pre_msg = concat(inputs[send], inputs[recv]) -> bf16 ----------------
__global__ void gather_kernel(const float* __restrict__ inputs) {
    int gid = blockIdx.x * blockDim.x + threadIdx.x;   // one thread = 8 bf16
    int e   = gid >> 6;
    int c8  = (gid & 63) << 3;   // 0..504
    int node = (c8 < 256) ? g_send_idx[e] : g_recv_idx[e];
    const float4* src = reinterpret_cast<const float4*>(inputs + (size_t)node * 256 + (c8 & 255));
    float4 v0 = src[0], v1 = src[1];
    uint4 o;
    o.x = pk(v0.x, v0.y); o.y = pk(v0.z, v0.w);
    o.z = pk(v1.x, v1.y); o.w = pk(v1.z, v1.w);
    *reinterpret_cast<uint4*>(g_pre + (size_t)e * 512 + c8) = o;
}

// ---------------- aug = concat(inputs, agg) -> bf16 ----------------
__global__ void concat_aug_kernel(const float* __restrict__ inputs) {
    int t = (blockIdx.x * blockDim.x + threadIdx.x) * 4;   // over 2048*512
    int row = t >> 9, col = t & 511;
    float4 v = (col < 256)
        ? *reinterpret_cast<const float4*>(inputs + (size_t)row * 256 + col)
        : *reinterpret_cast<const float4*>(g_agg + (size_t)row * 256 + (col - 256));
    uint2 o;
    o.x = pk(v.x, v.y);
    o.y = pk(v.z, v.w);
    *reinterpret_cast<uint2*>(g_aug + t) = o;
}

// ---------------- BM=128/BN=64 bf16 GEMM, cp.async 3-stage (edge layers) ----------------
template <bool RELU, bool SCATTER, bool RESID, bool OUTBF>
__global__ __launch_bounds__(256, 3) void gemm_cp_kernel(
    const __nv_bfloat16* __restrict__ A, const __nv_bfloat16* __restrict__ Wm,
    const float* __restrict__ bias, const float* __restrict__ resid,
    void* __restrict__ Cv, int Ntot) {

    constexpr int BM = 128, BN = 64, BK = 32;
    constexpr int SP = 20;
    constexpr int A_U32 = BM * SP;
    constexpr int B_U32 = BN * SP;
    constexpr int STG_U32 = A_U32 + B_U32;
    constexpr int STAGES = 3;
    __shared__ uint32_t sm[STAGES * STG_U32];
    __shared__ int ridx_s[BM];

    const int tid    = threadIdx.x;
    const int lane   = tid & 31;
    const int warp   = tid >> 5;
    const int warpM  = (warp & 3) * 32;
    const int warpN  = (warp >> 2) * 32;
    const int blockM = blockIdx.x * BM;
    const int blockN = blockIdx.y * BN;
    const uint32_t smBase = (uint32_t)__cvta_generic_to_shared(sm);

    if (SCATTER && tid < BM) ridx_s[tid] = g_recv_idx[blockM + tid];

    float acc[2][4][4];
#pragma unroll
    for (int mt = 0; mt < 2; mt++)
#pragma unroll
        for (int nt = 0; nt < 4; nt++)
#pragma unroll
            for (int j = 0; j < 4; j++) acc[mt][nt][j] = 0.f;

    const int ar0 = tid >> 2, ac = tid & 3;
    const int br  = tid >> 2;
    auto issue = [&](int kt, int stage) {
        uint32_t sa = smBase + (uint32_t)stage * STG_U32 * 4;
        cp16(sa + (uint32_t)(ar0 * SP + ac * 4) * 4,
             A + (size_t)(blockM + ar0) * 512 + kt * BK + ac * 8);
        cp16(sa + (uint32_t)((ar0 + 64) * SP + ac * 4) * 4,
             A + (size_t)(blockM + ar0 + 64) * 512 + kt * BK + ac * 8);
        cp16(sa + (uint32_t)(A_U32 + br * SP + ac * 4) * 4,
             Wm + (size_t)(blockN + br) * 512 + kt * BK + ac * 8);
    };

    issue(0, 0); CP_COMMIT();
    issue(1, 1); CP_COMMIT();

    const uint32_t aRowOff = (uint32_t)((lane & 15) * SP + ((lane >> 4) << 2)) * 4u;
    const uint32_t bRowOff = (uint32_t)(((lane & 7) + ((lane & 16) >> 1)) * SP +
                                        ((lane & 8) >> 1)) * 4u;

    constexpr int NKT = 512 / BK;
#pragma unroll 1
    for (int kt = 0; kt < NKT; kt++) {
        CP_WAIT1();
        __syncthreads();
        if (kt + 2 < NKT) issue(kt + 2, (kt + 2) % STAGES);
        CP_COMMIT();

        const uint32_t sbase = smBase + (uint32_t)(kt % STAGES) * STG_U32 * 4;
        const uint32_t asb = sbase + aRowOff;
        const uint32_t bsb = sbase + A_U32 * 4 + bRowOff;

#pragma unroll
        for (int ks = 0; ks < 2; ks++) {
            const uint32_t kcb = (uint32_t)(ks * 8 * 4);
            uint32_t a[2][4], b[4][2];
#pragma unroll
            for (int mt = 0; mt < 2; mt++)
                ldsm4(a[mt][0], a[mt][1], a[mt][2], a[mt][3],
                      asb + (uint32_t)((warpM + mt * 16) * SP * 4) + kcb);
#pragma unroll
            for (int ntp = 0; ntp < 2; ntp++)
                ldsm4(b[2 * ntp][0], b[2 * ntp][1], b[2 * ntp + 1][0], b[2 * ntp + 1][1],
                      bsb + (uint32_t)((warpN + ntp * 16) * SP * 4) + kcb);
#pragma unroll
            for (int mt = 0; mt < 2; mt++)
#pragma unroll
                for (int nt = 0; nt < 4; nt++)
                    mma_bf16(acc[mt][nt][0], acc[mt][nt][1], acc[mt][nt][2], acc[mt][nt][3],
                             a[mt][0], a[mt][1], a[mt][2], a[mt][3], b[nt][0], b[nt][1]);
        }
    }

#pragma unroll
    for (int mt = 0; mt < 2; mt++) {
        int r0 = warpM + mt * 16 + (lane >> 2);
        size_t gr0 = (size_t)blockM + r0;
        size_t gr1 = gr0 + 8;
        int node0 = 0, node1 = 0;
        if (SCATTER) { node0 = ridx_s[r0]; node1 = ridx_s[r0 + 8]; }
#pragma unroll
        for (int nt = 0; nt < 4; nt++) {
            int col = blockN + warpN + nt * 8 + (lane & 3) * 2;
            float bv0 = bias[col], bv1 = bias[col + 1];
            float v0 = acc[mt][nt][0] + bv0;
            float v1 = acc[mt][nt][1] + bv1;
            float v2 = acc[mt][nt][2] + bv0;
            float v3 = acc[mt][nt][3] + bv1;
            if (RELU) {
                v0 = fmaxf(v0, 0.f); v1 = fmaxf(v1, 0.f);
                v2 = fmaxf(v2, 0.f); v3 = fmaxf(v3, 0.f);
            }
            if (SCATTER) {
                float* p0 = &g_agg[(size_t)node0 * 256 + col];
                float* p1 = &g_agg[(size_t)node1 * 256 + col];
                asm volatile("red.global.add.v2.f32 [%0], {%1, %2};"
                             :: "l"(p0), "f"(v0), "f"(v1) : "memory");
                asm volatile("red.global.add.v2.f32 [%0], {%1, %2};"
                             :: "l"(p1), "f"(v2), "f"(v3) : "memory");
            } else if (RESID) {
                v0 += resid[gr0 * Ntot + col];
                v1 += resid[gr0 * Ntot + col + 1];
                v2 += resid[gr1 * Ntot + col];
                v3 += resid[gr1 * Ntot + col + 1];
                *reinterpret_cast<float2*>((float*)Cv + gr0 * Ntot + col) = make_float2(v0, v1);
                *reinterpret_cast<float2*>((float*)Cv + gr1 * Ntot + col) = make_float2(v2, v3);
            } else if (OUTBF) {
                __nv_bfloat16* C = (__nv_bfloat16*)Cv;
                *reinterpret_cast<__nv_bfloat162*>(C + gr0 * Ntot + col) =
                    __floats2bfloat162_rn(v0, v1);
                *reinterpret_cast<__nv_bfloat162*>(C + gr1 * Ntot + col) =
                    __floats2bfloat162_rn(v2, v3);
            }
        }
    }
}

// ---------------- BM=64/BN=64 bf16 GEMM (node layers: 4x more CTAs) ----------------
template <bool RELU, bool RESID, bool OUTBF>
__global__ __launch_bounds__(256, 4) void gemm_cp64_kernel(
    const __nv_bfloat16* __restrict__ A, const __nv_bfloat16* __restrict__ Wm,
    const float* __restrict__ bias, const float* __restrict__ resid,
    void* __restrict__ Cv, int Ntot) {

    constexpr int BM = 64, BN = 64, BK = 32;
    constexpr int SP = 20;
    constexpr int A_U32 = BM * SP;            // 1280
    constexpr int B_U32 = BN * SP;            // 1280
    constexpr int STG_U32 = A_U32 + B_U32;    // 2560 (10KB)
    constexpr int STAGES = 3;
    __shared__ uint32_t sm[STAGES * STG_U32];

    const int tid    = threadIdx.x;
    const int lane   = tid & 31;
    const int warp   = tid >> 5;
    const int warpM  = (warp & 1) * 32;       // 2 M-groups
    const int warpN  = (warp >> 1) * 16;      // 4 N-groups of 16 cols
    const int blockM = blockIdx.x * BM;
    const int blockN = blockIdx.y * BN;
    const uint32_t smBase = (uint32_t)__cvta_generic_to_shared(sm);

    float acc[2][2][4];
#pragma unroll
    for (int mt = 0; mt < 2; mt++)
#pragma unroll
        for (int nt = 0; nt < 2; nt++)
#pragma unroll
            for (int j = 0; j < 4; j++) acc[mt][nt][j] = 0.f;

    const int ar0 = tid >> 2, ac = tid & 3;   // 64 rows x 4 16B-chunks
    auto issue = [&](int kt, int stage) {
        uint32_t sa = smBase + (uint32_t)stage * STG_U32 * 4;
        cp16(sa + (uint32_t)(ar0 * SP + ac * 4) * 4,
             A + (size_t)(blockM + ar0) * 512 + kt * BK + ac * 8);
        cp16(sa + (uint32_t)(A_U32 + ar0 * SP + ac * 4) * 4,
             Wm + (size_t)(blockN + ar0) * 512 + kt * BK + ac * 8);
    };

    issue(0, 0); CP_COMMIT();
    issue(1, 1); CP_COMMIT();

    const uint32_t aRowOff = (uint32_t)((lane & 15) * SP + ((lane >> 4) << 2)) * 4u;
    const uint32_t bRowOff = (uint32_t)(((lane & 7) + ((lane & 16) >> 1)) * SP +
                                        ((lane & 8) >> 1)) * 4u;

    constexpr int NKT = 512 / BK;
#pragma unroll 1
    for (int kt = 0; kt < NKT; kt++) {
        CP_WAIT1();
        __syncthreads();
        if (kt + 2 < NKT) issue(kt + 2, (kt + 2) % STAGES);
        CP_COMMIT();

        const uint32_t sbase = smBase + (uint32_t)(kt % STAGES) * STG_U32 * 4;
        const uint32_t asb = sbase + aRowOff;
        const uint32_t bsb = sbase + A_U32 * 4 + bRowOff;

#pragma unroll
        for (int ks = 0; ks < 2; ks++) {
            const uint32_t kcb = (uint32_t)(ks * 8 * 4);
            uint32_t a[2][4], b[2][2];
#pragma unroll
            for (int mt = 0; mt < 2; mt++)
                ldsm4(a[mt][0], a[mt][1], a[mt][2], a[mt][3],
                      asb + (uint32_t)((warpM + mt * 16) * SP * 4) + kcb);
            ldsm4(b[0][0], b[0][1], b[1][0], b[1][1],
                  bsb + (uint32_t)(warpN * SP * 4) + kcb);
#pragma unroll
            for (int mt = 0; mt < 2; mt++)
#pragma unroll
                for (int nt = 0; nt < 2; nt++)
                    mma_bf16(acc[mt][nt][0], acc[mt][nt][1], acc[mt][nt][2], acc[mt][nt][3],
                             a[mt][0], a[mt][1], a[mt][2], a[mt][3], b[nt][0], b[nt][1]);
        }
    }

#pragma unroll
    for (int mt = 0; mt < 2; mt++) {
        int r0 = warpM + mt * 16 + (lane >> 2);
        size_t gr0 = (size_t)blockM + r0;
        size_t gr1 = gr0 + 8;
#pragma unroll
        for (int nt = 0; nt < 2; nt++) {
            int col = blockN + warpN + nt * 8 + (lane & 3) * 2;
            float bv0 = bias[col], bv1 = bias[col + 1];
            float v0 = acc[mt][nt][0] + bv0;
            float v1 = acc[mt][nt][1] + bv1;
            float v2 = acc[mt][nt][2] + bv0;
            float v3 = acc[mt][nt][3] + bv1;
            if (RELU) {
                v0 = fmaxf(v0, 0.f); v1 = fmaxf(v1, 0.f);
                v2 = fmaxf(v2, 0.f); v3 = fmaxf(v3, 0.f);
            }
            if (RESID) {
                v0 += resid[gr0 * Ntot + col];
                v1 += resid[gr0 * Ntot + col + 1];
                v2 += resid[gr1 * Ntot + col];
                v3 += resid[gr1 * Ntot + col + 1];
                *reinterpret_cast<float2*>((float*)Cv + gr0 * Ntot + col) = make_float2(v0, v1);
                *reinterpret_cast<float2*>((float*)Cv + gr1 * Ntot + col) = make_float2(v2, v3);
            } else if (OUTBF) {
                __nv_bfloat16* C = (__nv_bfloat16*)Cv;
                *reinterpret_cast<__nv_bfloat162*>(C + gr0 * Ntot + col) =
                    __floats2bfloat162_rn(v0, v1);
                *reinterpret_cast<__nv_bfloat162*>(C + gr1 * Ntot + col) =
                    __floats2bfloat162_rn(v2, v3);
            }
        }
    }
}

// ---------------- launch ----------------
extern "C" void kernel_launch(void* const* d_in, const int* in_sizes, int n_in,
                              void* d_out, int out_size) {
    const float* inputs   = (const float*)d_in[0];
    const float* rel_rec  = (const float*)d_in[1];
    const float* rel_send = (const float*)d_in[2];
    const float* msg_W1   = (const float*)d_in[3];
    const float* msg_b1   = (const float*)d_in[4];
    const float* msg_W2   = (const float*)d_in[5];
    const float* msg_b2   = (const float*)d_in[6];
    const float* out_W1   = (const float*)d_in[7];
    const float* out_b1   = (const float*)d_in[8];
    const float* out_W2   = (const float*)d_in[9];
    const float* out_b2   = (const float*)d_in[10];
    const float* out_W3   = (const float*)d_in[11];
    const float* out_b3   = (const float*)d_in[12];
    float* out = (float*)d_out;

    void *pre, *hid, *aug, *h1, *h2, *wbf;
    cudaGetSymbolAddress(&pre, g_pre);
    cudaGetSymbolAddress(&hid, g_hid);
    cudaGetSymbolAddress(&aug, g_aug);
    cudaGetSymbolAddress(&h1,  g_h1);
    cudaGetSymbolAddress(&h2,  g_h2);
    cudaGetSymbolAddress(&wbf, g_wbf);
    const __nv_bfloat16* wb = (const __nv_bfloat16*)wbf;

    // 1) indices from one-hot (early-exit scan)
    extract_idx_kernel<<<(2 * N_EDGES_C * 32) / 256, 256>>>(rel_rec, rel_send);
    // 2) zero aggregation buffer
    zero_agg_kernel<<<(N_NODES_C * 256 / 4) / 256, 256>>>();
    // 3) weights -> bf16
    convert_weights_kernel<<<1048576 / 4 / 256, 256>>>(msg_W1, msg_W2, out_W1, out_W2, out_W3);
    // 4) gather pre_msg bf16
    gather_kernel<<<(N_EDGES_C * 64) / 256, 256>>>(inputs);

    // 5) edge MLP layer 1: hid = relu(pre @ W1^T + b1)   [32768,512]
    gemm_cp_kernel<true, false, false, true>
        <<<dim3(N_EDGES_C / 128, 8), 256>>>(
            (const __nv_bfloat16*)pre, wb + W1_OFF, msg_b1, nullptr, hid, 512);

    // 6) edge MLP layer 2 + scatter-add into agg          [32768,256]
    gemm_cp_kernel<true, true, false, false>
        <<<dim3(N_EDGES_C / 128, 4), 256>>>(
            (const __nv_bfloat16*)hid, wb + W2_OFF, msg_b2, nullptr, nullptr, 256);

    // 7) aug = concat(inputs, agg) bf16
    concat_aug_kernel<<<(N_NODES_C * 512 / 4) / 256, 256>>>(inputs);

    // 8) node MLP layer 1: h1 = relu(aug @ outW1^T + b1)  [2048,512]  (256 CTAs)
    gemm_cp64_kernel<true, false, true>
        <<<dim3(N_NODES_C / 64, 8), 256>>>(
            (const __nv_bfloat16*)aug, wb + W3_OFF, out_b1, nullptr, h1, 512);

    // 9) node MLP layer 2: h2 = relu(h1 @ outW2^T + b2)   [2048,512]  (256 CTAs)
    gemm_cp64_kernel<true, false, true>
        <<<dim3(N_NODES_C / 64, 8), 256>>>(
            (const __nv_bfloat16*)h1, wb + W4_OFF, out_b2, nullptr, h2, 512);

    // 10) node MLP layer 3 + residual (f32 out)           [2048,256]  (128 CTAs)
    gemm_cp64_kernel<false, true, false>
        <<<dim3(N_NODES_C / 64, 4), 256>>>(
            (const __nv_bfloat16*)h2, wb + W5_OFF, out_b3, inputs, out, 256);
}

// round 7
// speedup vs baseline: 2.5561x; 1.4356x over previous
#include <cuda_runtime.h>
#include <cuda_bf16.h>
#include <cstdint>

#define N_NODES_C 2048
#define N_EDGES_C 32768

// ---------------- scratch (static device globals: allowed) ----------------
__device__ int            g_send_idx[N_EDGES_C];
__device__ int            g_recv_idx[N_EDGES_C];
__device__ __nv_bfloat16  g_inbf[N_NODES_C * 256];         // inputs bf16, 1MB
__device__ float          g_uv[(size_t)N_NODES_C * 1024];  // U | V  (f32), 8MB
__device__ __nv_bfloat16  g_hid[(size_t)N_EDGES_C * 512];  // edge hidden bf16, 32MB
__device__ float          g_agg[N_NODES_C * 256];          // aggregated messages (f32 atomics)
__device__ __nv_bfloat16  g_aug[N_NODES_C * 512];          // concat(inputs, agg) bf16
__device__ __nv_bfloat16  g_h1[(size_t)N_NODES_C * 512];
__device__ __nv_bfloat16  g_h2[(size_t)N_NODES_C * 512];
__device__ __nv_bfloat16  g_wbf[1048576];                  // all 5 weight mats, bf16
__device__ float          g_zerobias[1024];                // zero-initialized

// weight offsets inside g_wbf
#define W1_OFF 0         // msg_W1 remapped to [1024, 256] (W1a rows 0..511, W1b rows 512..1023)
#define W2_OFF 262144    // msg_W2 256x512
#define W3_OFF 393216    // out_W1 512x512
#define W4_OFF 655360    // out_W2 512x512
#define W5_OFF 917504    // out_W3 256x512

// ---------------- helpers ----------------
__device__ __forceinline__ uint32_t pk(float lo, float hi) {
    __nv_bfloat162 h = __floats2bfloat162_rn(lo, hi);
    return *reinterpret_cast<uint32_t*>(&h);
}
__device__ __forceinline__ void mma_bf16(float& d0, float& d1, float& d2, float& d3,
                                         uint32_t a0, uint32_t a1, uint32_t a2, uint32_t a3,
                                         uint32_t b0, uint32_t b1) {
    asm volatile(
        "mma.sync.aligned.m16n8k16.row.col.f32.bf16.bf16.f32 "
        "{%0,%1,%2,%3}, {%4,%5,%6,%7}, {%8,%9}, {%0,%1,%2,%3};"
        : "+f"(d0), "+f"(d1), "+f"(d2), "+f"(d3)
        : "r"(a0), "r"(a1), "r"(a2), "r"(a3), "r"(b0), "r"(b1));
}
__device__ __forceinline__ void ldsm4(uint32_t& r0, uint32_t& r1, uint32_t& r2, uint32_t& r3,
                                      uint32_t addr) {
    asm volatile("ldmatrix.sync.aligned.m8n8.x4.shared.b16 {%0,%1,%2,%3}, [%4];"
                 : "=r"(r0), "=r"(r1), "=r"(r2), "=r"(r3) : "r"(addr));
}
__device__ __forceinline__ void cp16(uint32_t dst, const void* src) {
    asm volatile("cp.async.cg.shared.global [%0], [%1], 16;" :: "r"(dst), "l"(src));
}
#define CP_COMMIT() asm volatile("cp.async.commit_group;" ::: "memory")
#define CP_WAIT1()  asm volatile("cp.async.wait_group 1;" ::: "memory")

// ---------------- index extraction: ballot early-exit (~53% traffic) ----------------
__global__ void extract_idx_kernel(const float* __restrict__ rel_rec,
                                   const float* __restrict__ rel_send) {
    int wg   = (blockIdx.x * blockDim.x + threadIdx.x) >> 5;
    int lane = threadIdx.x & 31;
    const float* mat;
    int* out;
    int e;
    if (wg < N_EDGES_C) { mat = rel_rec;  out = g_recv_idx; e = wg; }
    else                { mat = rel_send; out = g_send_idx; e = wg - N_EDGES_C; }

    const float4* p = reinterpret_cast<const float4*>(mat + (size_t)e * N_NODES_C) + lane;
    float4 v = __ldcs(p);
#pragma unroll 1
    for (int i = 0; i < 16; i++) {
        float4 nv;
        if (i < 15) nv = __ldcs(p + (i + 1) * 32);
        int base = (lane + i * 32) * 4;
        int f = -1;
        if (v.x != 0.f) f = base;
        if (v.y != 0.f) f = base + 1;
        if (v.z != 0.f) f = base + 2;
        if (v.w != 0.f) f = base + 3;
        if (__ballot_sync(0xffffffffu, f >= 0)) {
            if (f >= 0) out[e] = f;
            break;
        }
        v = nv;
    }
}

// ---------------- zero the aggregation buffer ----------------
__global__ void zero_agg_kernel() {
    int i = blockIdx.x * blockDim.x + threadIdx.x;
    reinterpret_cast<float4*>(g_agg)[i] = make_float4(0.f, 0.f, 0.f, 0.f);
}

// ---------------- convert weights + inputs to bf16 (W1 remapped to [1024,256]) ----------------
__global__ void convert_all_kernel(const float* __restrict__ w1, const float* __restrict__ w2,
                                   const float* __restrict__ w3, const float* __restrict__ w4,
                                   const float* __restrict__ w5, const float* __restrict__ inp) {
    int t = (blockIdx.x * blockDim.x + threadIdx.x) * 4;
    if (t < W2_OFF) {
        // msg_W1 [512,512] -> remap: row n cols<256 -> row n of [.,256]; cols>=256 -> row 512+n
        float4 v = *reinterpret_cast<const float4*>(w1 + t);
        int n = t >> 9, c = t & 511;
        int dst = ((c < 256 ? 0 : 512) + n) * 256 + (c & 255);
        uint2 o; o.x = pk(v.x, v.y); o.y = pk(v.z, v.w);
        *reinterpret_cast<uint2*>(g_wbf + dst) = o;
        return;
    }
    const float* src;
    __nv_bfloat16* dstp;
    int off;
    if      (t < W3_OFF)   { src = w2;  off = t - W2_OFF;   dstp = g_wbf + t; }
    else if (t < W4_OFF)   { src = w3;  off = t - W3_OFF;   dstp = g_wbf + t; }
    else if (t < W5_OFF)   { src = w4;  off = t - W4_OFF;   dstp = g_wbf + t; }
    else if (t < 1048576)  { src = w5;  off = t - W5_OFF;   dstp = g_wbf + t; }
    else                   { src = inp; off = t - 1048576;  dstp = g_inbf + (t - 1048576); }
    float4 v = *reinterpret_cast<const float4*>(src + off);
    uint2 o; o.x = pk(v.x, v.y); o.y = pk(v.z, v.w);
    *reinterpret_cast<uint2*>(dstp) = o;
}

// ---------------- hid[e] = relu(U[send[e]] + V[recv[e]] + b1) -> bf16 ----------------
__global__ void edge_combine_kernel(const float* __restrict__ b1) {
    int gid = blockIdx.x * blockDim.x + threadIdx.x;   // one thread = 8 cols
    int e   = gid >> 6;
    int c8  = (gid & 63) << 3;   // 0..504
    int s = g_send_idx[e], r = g_recv_idx[e];
    const float4* u = reinterpret_cast<const float4*>(g_uv + (size_t)s * 1024 + c8);
    const float4* v = reinterpret_cast<const float4*>(g_uv + (size_t)r * 1024 + 512 + c8);
    const float4* b = reinterpret_cast<const float4*>(b1 + c8);
    float4 u0 = u[0], u1 = u[1], v0 = v[0], v1 = v[1], b0 = b[0], bq = b[1];
    float x0 = fmaxf(u0.x + v0.x + b0.x, 0.f);
    float x1 = fmaxf(u0.y + v0.y + b0.y, 0.f);
    float x2 = fmaxf(u0.z + v0.z + b0.z, 0.f);
    float x3 = fmaxf(u0.w + v0.w + b0.w, 0.f);
    float x4 = fmaxf(u1.x + v1.x + bq.x, 0.f);
    float x5 = fmaxf(u1.y + v1.y + bq.y, 0.f);
    float x6 = fmaxf(u1.z + v1.z + bq.z, 0.f);
    float x7 = fmaxf(u1.w + v1.w + bq.w, 0.f);
    uint4 o;
    o.x = pk(x0, x1); o.y = pk(x2, x3); o.z = pk(x4, x5); o.w = pk(x6, x7);
    *reinterpret_cast<uint4*>(g_hid + (size_t)e * 512 + c8) = o;
}

// ---------------- aug = concat(inputs, agg) -> bf16 ----------------
__global__ void concat_aug_kernel(const float* __restrict__ inputs) {
    int t = (blockIdx.x * blockDim.x + threadIdx.x) * 4;
    int row = t >> 9, col = t & 511;
    float4 v = (col < 256)
        ? *reinterpret_cast<const float4*>(inputs + (size_t)row * 256 + col)
        : *reinterpret_cast<const float4*>(g_agg + (size_t)row * 256 + (col - 256));
    uint2 o;
    o.x = pk(v.x, v.y);
    o.y = pk(v.z, v.w);
    *reinterpret_cast<uint2*>(g_aug + t) = o;
}

// ---------------- BM=128/BN=64 bf16 GEMM, cp.async 3-stage (edge GEMM2) ----------------
template <bool RELU, bool SCATTER>
__global__ __launch_bounds__(256, 3) void gemm_cp_kernel(
    const __nv_bfloat16* __restrict__ A, const __nv_bfloat16* __restrict__ Wm,
    const float* __restrict__ bias, void* __restrict__ Cv, int Ntot) {

    constexpr int BM = 128, BN = 64, BK = 32;
    constexpr int SP = 20;
    constexpr int A_U32 = BM * SP;
    constexpr int B_U32 = BN * SP;
    constexpr int STG_U32 = A_U32 + B_U32;
    constexpr int STAGES = 3;
    __shared__ uint32_t sm[STAGES * STG_U32];
    __shared__ int ridx_s[BM];

    const int tid    = threadIdx.x;
    const int lane   = tid & 31;
    const int warp   = tid >> 5;
    const int warpM  = (warp & 3) * 32;
    const int warpN  = (warp >> 2) * 32;
    const int blockM = blockIdx.x * BM;
    const int blockN = blockIdx.y * BN;
    const uint32_t smBase = (uint32_t)__cvta_generic_to_shared(sm);

    if (SCATTER && tid < BM) ridx_s[tid] = g_recv_idx[blockM + tid];

    float acc[2][4][4];
#pragma unroll
    for (int mt = 0; mt < 2; mt++)
#pragma unroll
        for (int nt = 0; nt < 4; nt++)
#pragma unroll
            for (int j = 0; j < 4; j++) acc[mt][nt][j] = 0.f;

    const int ar0 = tid >> 2, ac = tid & 3;
    const int br  = tid >> 2;
    auto issue = [&](int kt, int stage) {
        uint32_t sa = smBase + (uint32_t)stage * STG_U32 * 4;
        cp16(sa + (uint32_t)(ar0 * SP + ac * 4) * 4,
             A + (size_t)(blockM + ar0) * 512 + kt * BK + ac * 8);
        cp16(sa + (uint32_t)((ar0 + 64) * SP + ac * 4) * 4,
             A + (size_t)(blockM + ar0 + 64) * 512 + kt * BK + ac * 8);
        cp16(sa + (uint32_t)(A_U32 + br * SP + ac * 4) * 4,
             Wm + (size_t)(blockN + br) * 512 + kt * BK + ac * 8);
    };

    issue(0, 0); CP_COMMIT();
    issue(1, 1); CP_COMMIT();

    const uint32_t aRowOff = (uint32_t)((lane & 15) * SP + ((lane >> 4) << 2)) * 4u;
    const uint32_t bRowOff = (uint32_t)(((lane & 7) + ((lane & 16) >> 1)) * SP +
                                        ((lane & 8) >> 1)) * 4u;

    constexpr int NKT = 512 / BK;
#pragma unroll 1
    for (int kt = 0; kt < NKT; kt++) {
        CP_WAIT1();
        __syncthreads();
        if (kt + 2 < NKT) issue(kt + 2, (kt + 2) % STAGES);
        CP_COMMIT();

        const uint32_t sbase = smBase + (uint32_t)(kt % STAGES) * STG_U32 * 4;
        const uint32_t asb = sbase + aRowOff;
        const uint32_t bsb = sbase + A_U32 * 4 + bRowOff;

#pragma unroll
        for (int ks = 0; ks < 2; ks++) {
            const uint32_t kcb = (uint32_t)(ks * 8 * 4);
            uint32_t a[2][4], b[4][2];
#pragma unroll
            for (int mt = 0; mt < 2; mt++)
                ldsm4(a[mt][0], a[mt][1], a[mt][2], a[mt][3],
                      asb + (uint32_t)((warpM + mt * 16) * SP * 4) + kcb);
#pragma unroll
            for (int ntp = 0; ntp < 2; ntp++)
                ldsm4(b[2 * ntp][0], b[2 * ntp][1], b[2 * ntp + 1][0], b[2 * ntp + 1][1],
                      bsb + (uint32_t)((warpN + ntp * 16) * SP * 4) + kcb);
#pragma unroll
            for (int mt = 0; mt < 2; mt++)
#pragma unroll
                for (int nt = 0; nt < 4; nt++)
                    mma_bf16(acc[mt][nt][0], acc[mt][nt][1], acc[mt][nt][2], acc[mt][nt][3],
                             a[mt][0], a[mt][1], a[mt][2], a[mt][3], b[nt][0], b[nt][1]);
        }
    }

#pragma unroll
    for (int mt = 0; mt < 2; mt++) {
        int r0 = warpM + mt * 16 + (lane >> 2);
        size_t gr0 = (size_t)blockM + r0;
        size_t gr1 = gr0 + 8;
        int node0 = 0, node1 = 0;
        if (SCATTER) { node0 = ridx_s[r0]; node1 = ridx_s[r0 + 8]; }
#pragma unroll
        for (int nt = 0; nt < 4; nt++) {
            int col = blockN + warpN + nt * 8 + (lane & 3) * 2;
            float bv0 = bias[col], bv1 = bias[col + 1];
            float v0 = acc[mt][nt][0] + bv0;
            float v1 = acc[mt][nt][1] + bv1;
            float v2 = acc[mt][nt][2] + bv0;
            float v3 = acc[mt][nt][3] + bv1;
            if (RELU) {
                v0 = fmaxf(v0, 0.f); v1 = fmaxf(v1, 0.f);
                v2 = fmaxf(v2, 0.f); v3 = fmaxf(v3, 0.f);
            }
            if (SCATTER) {
                float* p0 = &g_agg[(size_t)node0 * 256 + col];
                float* p1 = &g_agg[(size_t)node1 * 256 + col];
                asm volatile("red.global.add.v2.f32 [%0], {%1, %2};"
                             :: "l"(p0), "f"(v0), "f"(v1) : "memory");
                asm volatile("red.global.add.v2.f32 [%0], {%1, %2};"
                             :: "l"(p1), "f"(v2), "f"(v3) : "memory");
            } else {
                __nv_bfloat16* C = (__nv_bfloat16*)Cv;
                *reinterpret_cast<__nv_bfloat162*>(C + gr0 * Ntot + col) =
                    __floats2bfloat162_rn(v0, v1);
                *reinterpret_cast<__nv_bfloat162*>(C + gr1 * Ntot + col) =
                    __floats2bfloat162_rn(v2, v3);
            }
        }
    }
}

// ---------------- BM=64/BN=64 bf16 GEMM, templated K ----------------
// OMODE: 0 = bf16 store, 1 = f32 + resid store (no relu), 2 = f32 plain store
template <int KD, bool RELU, int OMODE>
__global__ __launch_bounds__(256, 4) void gemm_cp64_kernel(
    const __nv_bfloat16* __restrict__ A, const __nv_bfloat16* __restrict__ Wm,
    const float* __restrict__ bias, const float* __restrict__ resid,
    void* __restrict__ Cv, int Ntot) {

    constexpr int BM = 64, BN = 64, BK = 32;
    constexpr int SP = 20;
    constexpr int A_U32 = BM * SP;
    constexpr int B_U32 = BN * SP;
    constexpr int STG_U32 = A_U32 + B_U32;    // 2560 (10KB)
    constexpr int STAGES = 3;
    __shared__ uint32_t sm[STAGES * STG_U32];

    const int tid    = threadIdx.x;
    const int lane   = tid & 31;
    const int warp   = tid >> 5;
    const int warpM  = (warp & 1) * 32;
    const int warpN  = (warp >> 1) * 16;
    const int blockM = blockIdx.x * BM;
    const int blockN = blockIdx.y * BN;
    const uint32_t smBase = (uint32_t)__cvta_generic_to_shared(sm);

    float acc[2][2][4];
#pragma unroll
    for (int mt = 0; mt < 2; mt++)
#pragma unroll
        for (int nt = 0; nt < 2; nt++)
#pragma unroll
            for (int j = 0; j < 4; j++) acc[mt][nt][j] = 0.f;

    const int ar0 = tid >> 2, ac = tid & 3;
    auto issue = [&](int kt, int stage) {
        uint32_t sa = smBase + (uint32_t)stage * STG_U32 * 4;
        cp16(sa + (uint32_t)(ar0 * SP + ac * 4) * 4,
             A + (size_t)(blockM + ar0) * KD + kt * BK + ac * 8);
        cp16(sa + (uint32_t)(A_U32 + ar0 * SP + ac * 4) * 4,
             Wm + (size_t)(blockN + ar0) * KD + kt * BK + ac * 8);
    };

    issue(0, 0); CP_COMMIT();
    issue(1, 1); CP_COMMIT();

    const uint32_t aRowOff = (uint32_t)((lane & 15) * SP + ((lane >> 4) << 2)) * 4u;
    const uint32_t bRowOff = (uint32_t)(((lane & 7) + ((lane & 16) >> 1)) * SP +
                                        ((lane & 8) >> 1)) * 4u;

    constexpr int NKT = KD / BK;
#pragma unroll 1
    for (int kt = 0; kt < NKT; kt++) {
        CP_WAIT1();
        __syncthreads();
        if (kt + 2 < NKT) issue(kt + 2, (kt + 2) % STAGES);
        CP_COMMIT();

        const uint32_t sbase = smBase + (uint32_t)(kt % STAGES) * STG_U32 * 4;
        const uint32_t asb = sbase + aRowOff;
        const uint32_t bsb = sbase + A_U32 * 4 + bRowOff;

#pragma unroll
        for (int ks = 0; ks < 2; ks++) {
            const uint32_t kcb = (uint32_t)(ks * 8 * 4);
            uint32_t a[2][4], b[2][2];
#pragma unroll
            for (int mt = 0; mt < 2; mt++)
                ldsm4(a[mt][0], a[mt][1], a[mt][2], a[mt][3],
                      asb + (uint32_t)((warpM + mt * 16) * SP * 4) + kcb);
            ldsm4(b[0][0], b[0][1], b[1][0], b[1][1],
                  bsb + (uint32_t)(warpN * SP * 4) + kcb);
#pragma unroll
            for (int mt = 0; mt < 2; mt++)
#pragma unroll
                for (int nt = 0; nt < 2; nt++)
                    mma_bf16(acc[mt][nt][0], acc[mt][nt][1], acc[mt][nt][2], acc[mt][nt][3],
                             a[mt][0], a[mt][1], a[mt][2], a[mt][3], b[nt][0], b[nt][1]);
        }
    }

#pragma unroll
    for (int mt = 0; mt < 2; mt++) {
        int r0 = warpM + mt * 16 + (lane >> 2);
        size_t gr0 = (size_t)blockM + r0;
        size_t gr1 = gr0 + 8;
#pragma unroll
        for (int nt = 0; nt < 2; nt++) {
            int col = blockN + warpN + nt * 8 + (lane & 3) * 2;
            float bv0 = bias[col], bv1 = bias[col + 1];
            float v0 = acc[mt][nt][0] + bv0;
            float v1 = acc[mt][nt][1] + bv1;
            float v2 = acc[mt][nt][2] + bv0;
            float v3 = acc[mt][nt][3] + bv1;
            if (RELU) {
                v0 = fmaxf(v0, 0.f); v1 = fmaxf(v1, 0.f);
                v2 = fmaxf(v2, 0.f); v3 = fmaxf(v3, 0.f);
            }
            if (OMODE == 0) {
                __nv_bfloat16* C = (__nv_bfloat16*)Cv;
                *reinterpret_cast<__nv_bfloat162*>(C + gr0 * Ntot + col) =
                    __floats2bfloat162_rn(v0, v1);
                *reinterpret_cast<__nv_bfloat162*>(C + gr1 * Ntot + col) =
                    __floats2bfloat162_rn(v2, v3);
            } else if (OMODE == 1) {
                v0 += resid[gr0 * Ntot + col];
                v1 += resid[gr0 * Ntot + col + 1];
                v2 += resid[gr1 * Ntot + col];
                v3 += resid[gr1 * Ntot + col + 1];
                *reinterpret_cast<float2*>((float*)Cv + gr0 * Ntot + col) = make_float2(v0, v1);
                *reinterpret_cast<float2*>((float*)Cv + gr1 * Ntot + col) = make_float2(v2, v3);
            } else {
                *reinterpret_cast<float2*>((float*)Cv + gr0 * Ntot + col) = make_float2(v0, v1);
                *reinterpret_cast<float2*>((float*)Cv + gr1 * Ntot + col) = make_float2(v2, v3);
            }
        }
    }
}

// ---------------- launch ----------------
extern "C" void kernel_launch(void* const* d_in, const int* in_sizes, int n_in,
                              void* d_out, int out_size) {
    const float* inputs   = (const float*)d_in[0];
    const float* rel_rec  = (const float*)d_in[1];
    const float* rel_send = (const float*)d_in[2];
    const float* msg_W1   = (const float*)d_in[3];
    const float* msg_b1   = (const float*)d_in[4];
    const float* msg_W2   = (const float*)d_in[5];
    const float* msg_b2   = (const float*)d_in[6];
    const float* out_W1   = (const float*)d_in[7];
    const float* out_b1   = (const float*)d_in[8];
    const float* out_W2   = (const float*)d_in[9];
    const float* out_b2   = (const float*)d_in[10];
    const float* out_W3   = (const float*)d_in[11];
    const float* out_b3   = (const float*)d_in[12];
    float* out = (float*)d_out;

    void *inbf, *uv, *hid, *aug, *h1, *h2, *wbf, *zb;
    cudaGetSymbolAddress(&inbf, g_inbf);
    cudaGetSymbolAddress(&uv,   g_uv);
    cudaGetSymbolAddress(&hid,  g_hid);
    cudaGetSymbolAddress(&aug,  g_aug);
    cudaGetSymbolAddress(&h1,   g_h1);
    cudaGetSymbolAddress(&h2,   g_h2);
    cudaGetSymbolAddress(&wbf,  g_wbf);
    cudaGetSymbolAddress(&zb,   g_zerobias);
    const __nv_bfloat16* wb = (const __nv_bfloat16*)wbf;

    // 1) indices from one-hot (early-exit scan)
    extract_idx_kernel<<<(2 * N_EDGES_C * 32) / 256, 256>>>(rel_rec, rel_send);
    // 2) zero aggregation buffer
    zero_agg_kernel<<<(N_NODES_C * 256 / 4) / 256, 256>>>();
    // 3) weights (W1 remapped) + inputs -> bf16
    convert_all_kernel<<<1572864 / 4 / 256, 256>>>(msg_W1, msg_W2, out_W1, out_W2, out_W3,
                                                   inputs);

    // 4) UV = inputs_bf16 @ [W1a; W1b]^T   [2048,1024], K=256, f32 out, no bias/relu
    gemm_cp64_kernel<256, false, 2>
        <<<dim3(N_NODES_C / 64, 1024 / 64), 256>>>(
            (const __nv_bfloat16*)inbf, wb + W1_OFF, (const float*)zb, nullptr, uv, 1024);

    // 5) hid[e] = relu(U[send[e]] + V[recv[e]] + b1)  -> bf16  [32768,512]
    edge_combine_kernel<<<(N_EDGES_C * 64) / 256, 256>>>(msg_b1);

    // 6) edge MLP layer 2 + scatter-add into agg       [32768,256] K=512
    gemm_cp_kernel<true, true>
        <<<dim3(N_EDGES_C / 128, 4), 256>>>(
            (const __nv_bfloat16*)hid, wb + W2_OFF, msg_b2, nullptr, 256);

    // 7) aug = concat(inputs, agg) bf16
    concat_aug_kernel<<<(N_NODES_C * 512 / 4) / 256, 256>>>(inputs);

    // 8) node MLP layer 1: h1 = relu(aug @ outW1^T + b1)  [2048,512] K=512
    gemm_cp64_kernel<512, true, 0>
        <<<dim3(N_NODES_C / 64, 8), 256>>>(
            (const __nv_bfloat16*)aug, wb + W3_OFF, out_b1, nullptr, h1, 512);

    // 9) node MLP layer 2: h2 = relu(h1 @ outW2^T + b2)   [2048,512] K=512
    gemm_cp64_kernel<512, true, 0>
        <<<dim3(N_NODES_C / 64, 8), 256>>>(
            (const __nv_bfloat16*)h1, wb + W4_OFF, out_b2, nullptr, h2, 512);

    // 10) node MLP layer 3 + residual (f32 out)           [2048,256] K=512
    gemm_cp64_kernel<512, false, 1>
        <<<dim3(N_NODES_C / 64, 4), 256>>>(
            (const __nv_bfloat16*)h2, wb + W5_OFF, out_b3, inputs, out, 256);
}